// round 6
// baseline (speedup 1.0000x reference)
#include <cuda_runtime.h>
#include <cuda_bf16.h>
#include <cstdint>

#define BATCH  64
#define TSTEPS 2048
#define M_ROWS (BATCH * TSTEPS)   // 131072
#define HID    64
#define G4     256

typedef unsigned long long ull;

// ---------------------------------------------------------------------------
// Scratch
// ---------------------------------------------------------------------------
__device__ float    g_xg1[(size_t)M_ROWS * G4];   // layer1 gate preacts, natural layout
__device__ float    g_xg2[(size_t)M_ROWS * G4];   // layer2 gate preacts, natural layout
__device__ uint32_t g_xph[(size_t)M_ROWS * 64];   // x packed bf16x2 (hi)
__device__ uint32_t g_xpl[(size_t)M_ROWS * 64];   // x packed bf16x2 (lo residual)
__device__ uint4    g_wf1[32 * 8 * 32];           // W_ih1 fragment-ordered (hi+lo)
__device__ unsigned g_flag[BATCH];                // producer progress (rows ready)

// ---------------------------------------------------------------------------
// Helpers
// ---------------------------------------------------------------------------
__device__ __forceinline__ uint32_t packbf(float lo, float hi) {
    uint32_t r;
    asm("cvt.rn.bf16x2.f32 %0, %1, %2;" : "=r"(r) : "f"(hi), "f"(lo));
    return r;
}
__device__ __forceinline__ ull pack64(float lo, float hi) {
    ull r; asm("mov.b64 %0, {%1, %2};" : "=l"(r) : "f"(lo), "f"(hi)); return r;
}
__device__ __forceinline__ void unpack64(ull v, float& lo, float& hi) {
    asm("mov.b64 {%0, %1}, %2;" : "=f"(lo), "=f"(hi) : "l"(v));
}
__device__ __forceinline__ void fma2(ull& acc, ull a, ull b) {
    asm("fma.rn.f32x2 %0, %1, %2, %0;" : "+l"(acc) : "l"(a), "l"(b));
}
__device__ __forceinline__ ull add2(ull a, ull b) {
    ull r; asm("add.rn.f32x2 %0, %1, %2;" : "=l"(r) : "l"(a), "l"(b)); return r;
}
__device__ __forceinline__ float bf16_round(float f) {
    return __bfloat162float(__float2bfloat16_rn(f));
}
__device__ __forceinline__ float tanh_mufu(float x) {
    float y; asm("tanh.approx.f32 %0, %1;" : "=f"(y) : "f"(x)); return y;
}
__device__ __forceinline__ float sig_mufu(float x) {
    return fmaf(tanh_mufu(x * 0.5f), 0.5f, 0.5f);
}
__device__ __forceinline__ void mma16816(float* c, const uint32_t* a,
                                         uint32_t b0, uint32_t b1) {
    asm("mma.sync.aligned.m16n8k16.row.col.f32.bf16.bf16.f32 "
        "{%0,%1,%2,%3}, {%4,%5,%6,%7}, {%8,%9}, {%0,%1,%2,%3};"
        : "+f"(c[0]), "+f"(c[1]), "+f"(c[2]), "+f"(c[3])
        : "r"(a[0]), "r"(a[1]), "r"(a[2]), "r"(a[3]), "r"(b0), "r"(b1));
}
__device__ __forceinline__ unsigned ld_acq(const unsigned* p) {
    unsigned v;
    asm volatile("ld.acquire.gpu.global.u32 %0, [%1];" : "=r"(v) : "l"(p) : "memory");
    return v;
}
__device__ __forceinline__ void st_rel(unsigned* p, unsigned v) {
    asm volatile("st.release.gpu.global.u32 [%0], %1;" :: "l"(p), "r"(v) : "memory");
}

// 32-FFMA2 packed dot over h[64] (k-packed), software-pipelined LDS.128.
// hp_: 64 floats in smem (16-byte aligned). wv: 32 packed weight pairs.
__device__ __forceinline__ float dot32p(const float* hp_, const ull* wv) {
    const ulonglong2* hp = (const ulonglong2*)hp_;   // 16 entries
    ulonglong2 bufA[4], bufB[4];
#pragma unroll
    for (int i = 0; i < 4; i++) bufA[i] = hp[i];
    ull a0 = 0ull, a1 = 0ull, a2 = 0ull, a3 = 0ull;
#pragma unroll
    for (int c = 0; c < 4; c++) {
        ulonglong2* cur = (c & 1) ? bufB : bufA;
        ulonglong2* nxt = (c & 1) ? bufA : bufB;
        if (c < 3) {
#pragma unroll
            for (int i = 0; i < 4; i++) nxt[i] = hp[(c + 1) * 4 + i];
        }
        fma2(a0, cur[0].x, wv[c * 8 + 0]);
        fma2(a1, cur[0].y, wv[c * 8 + 1]);
        fma2(a2, cur[1].x, wv[c * 8 + 2]);
        fma2(a3, cur[1].y, wv[c * 8 + 3]);
        fma2(a0, cur[2].x, wv[c * 8 + 4]);
        fma2(a1, cur[2].y, wv[c * 8 + 5]);
        fma2(a2, cur[3].x, wv[c * 8 + 6]);
        fma2(a3, cur[3].y, wv[c * 8 + 7]);
    }
    ull s = add2(add2(a0, a1), add2(a2, a3));
    float lo, hi; unpack64(s, lo, hi);
    return lo + hi;
}

// ---------------------------------------------------------------------------
// Prep kernels
// ---------------------------------------------------------------------------
__global__ void prep_x_kernel(const float* __restrict__ x) {
    int i = blockIdx.x * blockDim.x + threadIdx.x;
    if (i < BATCH) g_flag[i] = 0;
    if (i >= M_ROWS * 64) return;
    float2 f = ((const float2*)x)[i];
    float hx = bf16_round(f.x), hy = bf16_round(f.y);
    g_xph[i] = packbf(f.x, f.y);
    g_xpl[i] = packbf(f.x - hx, f.y - hy);
}

__global__ void prep_w_kernel(const float* __restrict__ W) {
    const int KI = 8, K = 128;
    int total = 32 * KI * 32;
    int i = blockIdx.x * blockDim.x + threadIdx.x;
    if (i >= total) return;
    int lane = i & 31;
    int ki   = (i >> 5) % KI;
    int nt   = i / (32 * KI);
    int tig = lane & 3, gid = lane >> 2;
    int n  = nt * 8 + gid;
    int k0 = ki * 16 + tig * 2;
    const float* Wn = W + (size_t)n * K;
    float w00 = Wn[k0],     w01 = Wn[k0 + 1];
    float w10 = Wn[k0 + 8], w11 = Wn[k0 + 9];
    uint4 v;
    v.x = packbf(w00, w01);
    v.y = packbf(w10, w11);
    v.z = packbf(w00 - bf16_round(w00), w01 - bf16_round(w01));
    v.w = packbf(w10 - bf16_round(w10), w11 - bf16_round(w11));
    g_wf1[(nt * KI + ki) * 32 + lane] = v;
}

// ---------------------------------------------------------------------------
// GEMM1: g_xg1 = x @ W_ih1^T + bias (3-term bf16 split), natural layout out.
// ---------------------------------------------------------------------------
__global__ __launch_bounds__(256, 2) void gemm_kernel(
    const float* __restrict__ bias_a, const float* __restrict__ bias_b)
{
    const int KI = 8, PPR = 64;
    int tid = threadIdx.x;
    int lane = tid & 31, wid = tid >> 5;
    int tig = lane & 3, gid = lane >> 2;
    int wm = wid & 3, wn = wid >> 2;
    int rb = blockIdx.x * 64 + wm * 16;
    int ntBase = (blockIdx.y * 2 + wn) * 8;

    float acc[8][4];
#pragma unroll
    for (int j = 0; j < 8; j++)
#pragma unroll
        for (int q = 0; q < 4; q++) acc[j][q] = 0.0f;

#pragma unroll
    for (int ki = 0; ki < KI; ki++) {
        uint32_t a[4], al[4];
        size_t r0 = (size_t)(rb + gid) * PPR + ki * 8;
        a[0]  = __ldg(g_xph + r0 + tig);
        a[1]  = __ldg(g_xph + r0 + 8 * PPR + tig);
        a[2]  = __ldg(g_xph + r0 + 4 + tig);
        a[3]  = __ldg(g_xph + r0 + 8 * PPR + 4 + tig);
        al[0] = __ldg(g_xpl + r0 + tig);
        al[1] = __ldg(g_xpl + r0 + 8 * PPR + tig);
        al[2] = __ldg(g_xpl + r0 + 4 + tig);
        al[3] = __ldg(g_xpl + r0 + 8 * PPR + 4 + tig);
#pragma unroll
        for (int j = 0; j < 8; j++) {
            uint4 bf = __ldg(&g_wf1[((ntBase + j) * KI + ki) * 32 + lane]);
            mma16816(acc[j], a,  bf.x, bf.y);
            mma16816(acc[j], a,  bf.z, bf.w);
            mma16816(acc[j], al, bf.x, bf.y);
        }
    }

#pragma unroll
    for (int j = 0; j < 8; j++) {
        int nc = (ntBase + j) * 8 + tig * 2;
        float bs0 = __ldg(bias_a + nc) + __ldg(bias_b + nc);
        float bs1 = __ldg(bias_a + nc + 1) + __ldg(bias_b + nc + 1);
        size_t r = (size_t)(rb + gid);
        *(float2*)(g_xg1 + r * G4 + nc) =
            make_float2(acc[j][0] + bs0, acc[j][1] + bs1);
        *(float2*)(g_xg1 + (r + 8) * G4 + nc) =
            make_float2(acc[j][2] + bs0, acc[j][3] + bs1);
    }
}

// ---------------------------------------------------------------------------
// PRODUCER (512 thr): warps 0-7 layer1 rec (1 gate/thread), warps 8-15 GEMV
// producing g_xg2 rows (mask1 folded into weights). One __syncthreads/step.
// Gate mapping (rec): warp w, lane l: gatetype gt = l>>3 (i,f,g,o),
// unit u = 8w + (l&7); gate index = gt*64 + u. Pointwise exchange via 3 bfly.
// ---------------------------------------------------------------------------
__global__ __launch_bounds__(512, 1) void producer_kernel(
    const float* __restrict__ Whh1, const float* __restrict__ mask1,
    const float* __restrict__ Wih2, const float* __restrict__ bih2,
    const float* __restrict__ bhh2)
{
    __shared__ alignas(16) float hq[2][64];
    int tid = threadIdx.x;
    int b = blockIdx.x;
    int lane = tid & 31, w = tid >> 5;

    if (w < 8) {
        // ---- layer1 recurrence ----
        int gt = lane >> 3;
        int u  = (w << 3) + (lane & 7);
        int gidx = gt * 64 + u;
        ull wv[32];
#pragma unroll
        for (int k = 0; k < 32; k++)
            wv[k] = pack64(__ldg(Whh1 + (size_t)gidx * 64 + 2 * k),
                           __ldg(Whh1 + (size_t)gidx * 64 + 2 * k + 1));
        if (tid < 64) { hq[0][tid] = 0.0f; hq[1][tid] = 0.0f; }
        float c = 0.0f;
        const float* xgp = g_xg1 + (size_t)b * TSTEPS * G4 + gidx;
        __syncthreads();                                   // bar0
        float xc = __ldg(xgp), xn = __ldg(xgp + G4);
        for (int t = 0; t < TSTEPS; t++) {
            int cur = t & 1;
            float xf = 0.0f;
            if (t + 2 < TSTEPS) xf = __ldg(xgp + (size_t)(t + 2) * G4);
            float pre = dot32p(hq[cur], wv) + xc;
            float A = (gt == 2) ? tanh_mufu(pre) : sig_mufu(pre);
            float fA = __shfl_xor_sync(0xffffffffu, A, 8);
            float gA = __shfl_xor_sync(0xffffffffu, A, 16);
            float oA = __shfl_xor_sync(0xffffffffu, A, 24);
            if (lane < 8) {                                // i-lanes own unit u
                c = fA * c + A * gA;
                float h = oA * tanh_mufu(c);
                hq[cur ^ 1][u] = h;
            }
            xc = xn; xn = xf;
            __syncthreads();                               // 1 bar / step
        }
    } else {
        // ---- GEMV: xg2 row t-1 = (W_ih2 * mask1) @ h(t-1) + bias ----
        int s = tid - 256;                                 // gate 0..255
        ull wv2[32];
#pragma unroll
        for (int k = 0; k < 32; k++) {
            float m0 = __ldg(mask1 + b * 64 + 2 * k);
            float m1 = __ldg(mask1 + b * 64 + 2 * k + 1);
            wv2[k] = pack64(__ldg(Wih2 + (size_t)s * 64 + 2 * k) * m0,
                            __ldg(Wih2 + (size_t)s * 64 + 2 * k + 1) * m1);
        }
        float bias = __ldg(bih2 + s) + __ldg(bhh2 + s);
        float* dst = g_xg2 + (size_t)b * TSTEPS * G4 + s;
        __syncthreads();                                   // bar0
        for (int t = 0; t < TSTEPS; t++) {
            int cur = t & 1;
            if (t > 0)
                dst[(size_t)(t - 1) * G4] = dot32p(hq[cur], wv2) + bias;
            __syncthreads();
            if (tid == 256 && (t & 3) == 3)
                st_rel(&g_flag[b], (unsigned)(t - 1));     // rows 0..t-2 ready
        }
        // final row T-1: h(T-1) is in hq[TSTEPS & 1] == hq[0]
        dst[(size_t)(TSTEPS - 1) * G4] = dot32p(hq[0], wv2) + bias;
        if (tid == 256) st_rel(&g_flag[b], (unsigned)TSTEPS);
    }
}

// ---------------------------------------------------------------------------
// CONSUMER (256 thr): layer2 recurrence, 1 gate/thread, gated by g_flag.
// ---------------------------------------------------------------------------
__global__ __launch_bounds__(256, 1) void consumer_kernel(
    const float* __restrict__ Whh2, const float* __restrict__ mask2,
    float* __restrict__ out)
{
    __shared__ alignas(16) float hq[2][64];
    int tid = threadIdx.x;
    int b = blockIdx.x;
    int lane = tid & 31, w = tid >> 5;
    int gt = lane >> 3;
    int u  = (w << 3) + (lane & 7);
    int gidx = gt * 64 + u;

    ull wv[32];
#pragma unroll
    for (int k = 0; k < 32; k++)
        wv[k] = pack64(__ldg(Whh2 + (size_t)gidx * 64 + 2 * k),
                       __ldg(Whh2 + (size_t)gidx * 64 + 2 * k + 1));
    float mval = __ldg(mask2 + b * 64 + u);
    if (tid < 64) { hq[0][tid] = 0.0f; hq[1][tid] = 0.0f; }
    float c = 0.0f;
    const float* xgp = g_xg2 + (size_t)b * TSTEPS * G4 + gidx;
    unsigned avail = 0;
    __syncthreads();                                       // bar0
    while (avail < 2u) { avail = ld_acq(&g_flag[b]); if (avail < 2u) __nanosleep(32); }
    float xc = __ldg(xgp), xn = __ldg(xgp + G4);
    for (int t = 0; t < TSTEPS; t++) {
        int cur = t & 1;
        float xf = 0.0f;
        if (t + 2 < TSTEPS) {
            unsigned need = (unsigned)(t + 3);
            while (avail < need) { avail = ld_acq(&g_flag[b]); if (avail < need) __nanosleep(32); }
            xf = __ldg(xgp + (size_t)(t + 2) * G4);
        }
        float pre = dot32p(hq[cur], wv) + xc;
        float A = (gt == 2) ? tanh_mufu(pre) : sig_mufu(pre);
        float fA = __shfl_xor_sync(0xffffffffu, A, 8);
        float gA = __shfl_xor_sync(0xffffffffu, A, 16);
        float oA = __shfl_xor_sync(0xffffffffu, A, 24);
        if (lane < 8) {
            c = fA * c + A * gA;
            float h = oA * tanh_mufu(c);
            hq[cur ^ 1][u] = h;
            out[((size_t)b * TSTEPS + t) * HID + u] = fmaxf(h * mval, 0.0f);
        }
        xc = xn; xn = xf;
        __syncthreads();
    }
}

// ---------------------------------------------------------------------------
// Launch
// ---------------------------------------------------------------------------
extern "C" void kernel_launch(void* const* d_in, const int* in_sizes, int n_in,
                              void* d_out, int out_size) {
    const float* x     = (const float*)d_in[0];
    const float* W_ih1 = (const float*)d_in[1];
    const float* W_hh1 = (const float*)d_in[2];
    const float* b_ih1 = (const float*)d_in[3];
    const float* b_hh1 = (const float*)d_in[4];
    const float* W_ih2 = (const float*)d_in[5];
    const float* W_hh2 = (const float*)d_in[6];
    const float* b_ih2 = (const float*)d_in[7];
    const float* b_hh2 = (const float*)d_in[8];
    const float* mask1 = (const float*)d_in[9];
    const float* mask2 = (const float*)d_in[10];
    float* out = (float*)d_out;

    prep_x_kernel<<<(M_ROWS * 64) / 256, 256>>>(x);
    prep_w_kernel<<<(32 * 8 * 32 + 127) / 128, 128>>>(W_ih1);
    gemm_kernel<<<dim3(M_ROWS / 64, 2), 256>>>(b_ih1, b_hh1);
    // pipelined recurrences: producers then consumers (co-resident, 128 CTAs)
    producer_kernel<<<BATCH, 512>>>(W_hh1, mask1, W_ih2, b_ih2, b_hh2);
    consumer_kernel<<<BATCH, 256>>>(W_hh2, mask2, out);
}

// round 11
// speedup vs baseline: 1.2880x; 1.2880x over previous
#include <cuda_runtime.h>
#include <cuda_bf16.h>
#include <cstdint>

#define BATCH  64
#define TSTEPS 2048
#define M_ROWS (BATCH * TSTEPS)   // 131072
#define HID    64
#define G4     256

typedef unsigned long long ull;

// ---------------------------------------------------------------------------
// Scratch
// ---------------------------------------------------------------------------
__device__ float    g_xg1[(size_t)M_ROWS * G4];   // layer1 gate preacts
__device__ float    g_xg2[(size_t)M_ROWS * G4];   // layer2 gate preacts
__device__ uint32_t g_xph[(size_t)M_ROWS * 64];   // x packed bf16x2 (hi)
__device__ uint32_t g_xpl[(size_t)M_ROWS * 64];   // x packed bf16x2 (lo residual)
__device__ uint4    g_wf1[32 * 8 * 32];           // W_ih1 fragment-ordered (hi+lo)
__device__ unsigned g_flag[BATCH];                // xg2 rows ready per sequence

// ---------------------------------------------------------------------------
// Helpers
// ---------------------------------------------------------------------------
__device__ __forceinline__ uint32_t packbf(float lo, float hi) {
    uint32_t r;
    asm("cvt.rn.bf16x2.f32 %0, %1, %2;" : "=r"(r) : "f"(hi), "f"(lo));
    return r;
}
__device__ __forceinline__ ull pack64(float lo, float hi) {
    ull r; asm("mov.b64 %0, {%1, %2};" : "=l"(r) : "f"(lo), "f"(hi)); return r;
}
__device__ __forceinline__ void unpack64(ull v, float& lo, float& hi) {
    asm("mov.b64 {%0, %1}, %2;" : "=f"(lo), "=f"(hi) : "l"(v));
}
__device__ __forceinline__ void fma2(ull& acc, ull a, ull b) {
    asm("fma.rn.f32x2 %0, %1, %2, %0;" : "+l"(acc) : "l"(a), "l"(b));
}
__device__ __forceinline__ ull add2(ull a, ull b) {
    ull r; asm("add.rn.f32x2 %0, %1, %2;" : "=l"(r) : "l"(a), "l"(b)); return r;
}
__device__ __forceinline__ float bf16_round(float f) {
    return __bfloat162float(__float2bfloat16_rn(f));
}
__device__ __forceinline__ float tanh_mufu(float x) {
    float y; asm("tanh.approx.f32 %0, %1;" : "=f"(y) : "f"(x)); return y;
}
__device__ __forceinline__ float sig_mufu(float x) {
    return fmaf(tanh_mufu(x * 0.5f), 0.5f, 0.5f);
}
__device__ __forceinline__ void mma16816(float* c, const uint32_t* a,
                                         uint32_t b0, uint32_t b1) {
    asm("mma.sync.aligned.m16n8k16.row.col.f32.bf16.bf16.f32 "
        "{%0,%1,%2,%3}, {%4,%5,%6,%7}, {%8,%9}, {%0,%1,%2,%3};"
        : "+f"(c[0]), "+f"(c[1]), "+f"(c[2]), "+f"(c[3])
        : "r"(a[0]), "r"(a[1]), "r"(a[2]), "r"(a[3]), "r"(b0), "r"(b1));
}
__device__ __forceinline__ unsigned ld_acq(const unsigned* p) {
    unsigned v;
    asm volatile("ld.acquire.gpu.global.u32 %0, [%1];" : "=r"(v) : "l"(p) : "memory");
    return v;
}
__device__ __forceinline__ void st_rel(unsigned* p, unsigned v) {
    asm volatile("st.release.gpu.global.u32 [%0], %1;" :: "l"(p), "r"(v) : "memory");
}

// 32-FFMA2 packed dot over h[64], software-pipelined LDS.128.
__device__ __forceinline__ float dot32p(const float* hp_, const ull* wv) {
    const ulonglong2* hp = (const ulonglong2*)hp_;   // 16 entries
    ulonglong2 bufA[4], bufB[4];
#pragma unroll
    for (int i = 0; i < 4; i++) bufA[i] = hp[i];
    ull a0 = 0ull, a1 = 0ull, a2 = 0ull, a3 = 0ull;
#pragma unroll
    for (int c = 0; c < 4; c++) {
        ulonglong2* cur = (c & 1) ? bufB : bufA;
        ulonglong2* nxt = (c & 1) ? bufA : bufB;
        if (c < 3) {
#pragma unroll
            for (int i = 0; i < 4; i++) nxt[i] = hp[(c + 1) * 4 + i];
        }
        fma2(a0, cur[0].x, wv[c * 8 + 0]);
        fma2(a1, cur[0].y, wv[c * 8 + 1]);
        fma2(a2, cur[1].x, wv[c * 8 + 2]);
        fma2(a3, cur[1].y, wv[c * 8 + 3]);
        fma2(a0, cur[2].x, wv[c * 8 + 4]);
        fma2(a1, cur[2].y, wv[c * 8 + 5]);
        fma2(a2, cur[3].x, wv[c * 8 + 6]);
        fma2(a3, cur[3].y, wv[c * 8 + 7]);
    }
    ull s = add2(add2(a0, a1), add2(a2, a3));
    float lo, hi; unpack64(s, lo, hi);
    return lo + hi;
}

// ---------------------------------------------------------------------------
// Prep kernels
// ---------------------------------------------------------------------------
__global__ void prep_x_kernel(const float* __restrict__ x) {
    int i = blockIdx.x * blockDim.x + threadIdx.x;
    if (i < BATCH) g_flag[i] = 0;
    if (i >= M_ROWS * 64) return;
    float2 f = ((const float2*)x)[i];
    float hx = bf16_round(f.x), hy = bf16_round(f.y);
    g_xph[i] = packbf(f.x, f.y);
    g_xpl[i] = packbf(f.x - hx, f.y - hy);
}

__global__ void prep_w_kernel(const float* __restrict__ W) {
    const int KI = 8, K = 128;
    int total = 32 * KI * 32;
    int i = blockIdx.x * blockDim.x + threadIdx.x;
    if (i >= total) return;
    int lane = i & 31;
    int ki   = (i >> 5) % KI;
    int nt   = i / (32 * KI);
    int tig = lane & 3, gid = lane >> 2;
    int n  = nt * 8 + gid;
    int k0 = ki * 16 + tig * 2;
    const float* Wn = W + (size_t)n * K;
    float w00 = Wn[k0],     w01 = Wn[k0 + 1];
    float w10 = Wn[k0 + 8], w11 = Wn[k0 + 9];
    uint4 v;
    v.x = packbf(w00, w01);
    v.y = packbf(w10, w11);
    v.z = packbf(w00 - bf16_round(w00), w01 - bf16_round(w01));
    v.w = packbf(w10 - bf16_round(w10), w11 - bf16_round(w11));
    g_wf1[(nt * KI + ki) * 32 + lane] = v;
}

// ---------------------------------------------------------------------------
// GEMM1: g_xg1 = x @ W_ih1^T + bias (3-term bf16 split), natural layout.
// ---------------------------------------------------------------------------
__global__ __launch_bounds__(256, 2) void gemm_kernel(
    const float* __restrict__ bias_a, const float* __restrict__ bias_b)
{
    const int KI = 8, PPR = 64;
    int tid = threadIdx.x;
    int lane = tid & 31, wid = tid >> 5;
    int tig = lane & 3, gid = lane >> 2;
    int wm = wid & 3, wn = wid >> 2;
    int rb = blockIdx.x * 64 + wm * 16;
    int ntBase = (blockIdx.y * 2 + wn) * 8;

    float acc[8][4];
#pragma unroll
    for (int j = 0; j < 8; j++)
#pragma unroll
        for (int q = 0; q < 4; q++) acc[j][q] = 0.0f;

#pragma unroll
    for (int ki = 0; ki < KI; ki++) {
        uint32_t a[4], al[4];
        size_t r0 = (size_t)(rb + gid) * PPR + ki * 8;
        a[0]  = __ldg(g_xph + r0 + tig);
        a[1]  = __ldg(g_xph + r0 + 8 * PPR + tig);
        a[2]  = __ldg(g_xph + r0 + 4 + tig);
        a[3]  = __ldg(g_xph + r0 + 8 * PPR + 4 + tig);
        al[0] = __ldg(g_xpl + r0 + tig);
        al[1] = __ldg(g_xpl + r0 + 8 * PPR + tig);
        al[2] = __ldg(g_xpl + r0 + 4 + tig);
        al[3] = __ldg(g_xpl + r0 + 8 * PPR + 4 + tig);
#pragma unroll
        for (int j = 0; j < 8; j++) {
            uint4 bf = __ldg(&g_wf1[((ntBase + j) * KI + ki) * 32 + lane]);
            mma16816(acc[j], a,  bf.x, bf.y);
            mma16816(acc[j], a,  bf.z, bf.w);
            mma16816(acc[j], al, bf.x, bf.y);
        }
    }

#pragma unroll
    for (int j = 0; j < 8; j++) {
        int nc = (ntBase + j) * 8 + tig * 2;
        float bs0 = __ldg(bias_a + nc) + __ldg(bias_b + nc);
        float bs1 = __ldg(bias_a + nc + 1) + __ldg(bias_b + nc + 1);
        size_t r = (size_t)(rb + gid);
        *(float2*)(g_xg1 + r * G4 + nc) =
            make_float2(acc[j][0] + bs0, acc[j][1] + bs1);
        *(float2*)(g_xg1 + (r + 8) * G4 + nc) =
            make_float2(acc[j][2] + bs0, acc[j][3] + bs1);
    }
}

// ---------------------------------------------------------------------------
// Fused kernel: 128 CTAs x 512 threads (single wave, co-resident).
//  Producer CTA (b<64): warps 0-7 layer1 rec -> fp32 h*mask1 into 64-deep
//    smem ring; warps 8-15 tensor-core chunk GEMM (16 xg2 rows / chunk).
//    Publish: stores -> block barrier -> tid 256 __threadfence + st.release.
//  Consumer CTA (b>=64): warps 0-7 layer2 rec gated on g_flag, reading
//    g_xg2 with PLAIN COHERENT loads (the R7-R9 bug was __ldg here: the
//    read-only path may be hoisted/served stale across the acquire).
// ---------------------------------------------------------------------------
__global__ __launch_bounds__(512, 1) void fused_kernel(
    const float* __restrict__ Whh1, const float* __restrict__ mask1,
    const float* __restrict__ Wih2, const float* __restrict__ bih2,
    const float* __restrict__ bhh2,
    const float* __restrict__ Whh2, const float* __restrict__ mask2,
    float* __restrict__ out)
{
    __shared__ alignas(16) float hq[2][64];
    __shared__ alignas(16) float ringf[64][64];    // fp32 h*mask ring (16KB)

    int tid = threadIdx.x;
    bool producer = blockIdx.x < BATCH;
    int b = producer ? blockIdx.x : blockIdx.x - BATCH;
    int lane = tid & 31, w = tid >> 5;
    int tig = lane & 3, gid = lane >> 2;

    if (producer) {
        if (w < 8) {
            // ======== layer1 recurrence ========
            int gt = lane >> 3;
            int u  = (w << 3) + (lane & 7);
            int gidx = gt * 64 + u;
            ull wv[32];
#pragma unroll
            for (int k = 0; k < 32; k++)
                wv[k] = pack64(__ldg(Whh1 + (size_t)gidx * 64 + 2 * k),
                               __ldg(Whh1 + (size_t)gidx * 64 + 2 * k + 1));
            float mval = (lane < 8) ? __ldg(mask1 + b * 64 + u) : 0.0f;
            if (tid < 64) { hq[0][tid] = 0.0f; hq[1][tid] = 0.0f; }
            float c = 0.0f;
            const float* xgp = g_xg1 + (size_t)b * TSTEPS * G4 + gidx;
            __syncthreads();                               // bar0
            float x0 = __ldg(xgp);
            float x1 = __ldg(xgp + G4);
            float x2 = __ldg(xgp + 2 * G4);
            float x3 = __ldg(xgp + 3 * G4);
            for (int t = 0; t < TSTEPS; t++) {
                int cur = t & 1;
                float xc = x0; x0 = x1; x1 = x2; x2 = x3;
                if (t + 4 < TSTEPS) x3 = __ldg(xgp + (size_t)(t + 4) * G4);
                float pre = dot32p(hq[cur], wv) + xc;
                float A = (gt == 2) ? tanh_mufu(pre) : sig_mufu(pre);
                float fA = __shfl_xor_sync(0xffffffffu, A, 8);
                float gA = __shfl_xor_sync(0xffffffffu, A, 16);
                float oA = __shfl_xor_sync(0xffffffffu, A, 24);
                if (lane < 8) {
                    c = fA * c + A * gA;
                    float h = oA * tanh_mufu(c);
                    hq[cur ^ 1][u] = h;
                    ringf[t & 63][u] = h * mval;           // fp32 ring write
                }
                __syncthreads();                           // 1 bar / step
            }
            __syncthreads();                               // post (final chunk)
        } else {
            // ======== tensor-core chunk GEMM (xg2 rows, 16/chunk) ========
            int ws = w - 8;                                 // 0..7, 4 n-tiles each
            uint32_t Bh0[4][4], Bh1[4][4], Bl0[4][4], Bl1[4][4];
            float bias0[4], bias1[4];
#pragma unroll
            for (int n4 = 0; n4 < 4; n4++) {
                int nt = ws * 4 + n4;
                int n0 = nt * 8 + gid;
#pragma unroll
                for (int kt = 0; kt < 4; kt++) {
                    int k0 = kt * 16 + tig * 2;
                    float w00 = __ldg(Wih2 + (size_t)n0 * 64 + k0);
                    float w01 = __ldg(Wih2 + (size_t)n0 * 64 + k0 + 1);
                    float w10 = __ldg(Wih2 + (size_t)n0 * 64 + k0 + 8);
                    float w11 = __ldg(Wih2 + (size_t)n0 * 64 + k0 + 9);
                    Bh0[n4][kt] = packbf(w00, w01);
                    Bh1[n4][kt] = packbf(w10, w11);
                    Bl0[n4][kt] = packbf(w00 - bf16_round(w00), w01 - bf16_round(w01));
                    Bl1[n4][kt] = packbf(w10 - bf16_round(w10), w11 - bf16_round(w11));
                }
                int col = nt * 8 + 2 * tig;
                bias0[n4] = __ldg(bih2 + col) + __ldg(bhh2 + col);
                bias1[n4] = __ldg(bih2 + col + 1) + __ldg(bhh2 + col + 1);
            }
            __syncthreads();                               // bar0

            auto do_chunk = [&](int r0) {
                int ra = (r0 + gid) & 63, rb_ = (r0 + gid + 8) & 63;
                uint32_t Ah[4][4], Al[4][4];
#pragma unroll
                for (int kt = 0; kt < 4; kt++) {
                    float2 p0 = *(const float2*)&ringf[ra][16 * kt + 2 * tig];
                    float2 p1 = *(const float2*)&ringf[rb_][16 * kt + 2 * tig];
                    float2 p2 = *(const float2*)&ringf[ra][16 * kt + 2 * tig + 8];
                    float2 p3 = *(const float2*)&ringf[rb_][16 * kt + 2 * tig + 8];
                    Ah[kt][0] = packbf(p0.x, p0.y);
                    Ah[kt][1] = packbf(p1.x, p1.y);
                    Ah[kt][2] = packbf(p2.x, p2.y);
                    Ah[kt][3] = packbf(p3.x, p3.y);
                    Al[kt][0] = packbf(p0.x - bf16_round(p0.x), p0.y - bf16_round(p0.y));
                    Al[kt][1] = packbf(p1.x - bf16_round(p1.x), p1.y - bf16_round(p1.y));
                    Al[kt][2] = packbf(p2.x - bf16_round(p2.x), p2.y - bf16_round(p2.y));
                    Al[kt][3] = packbf(p3.x - bf16_round(p3.x), p3.y - bf16_round(p3.y));
                }
#pragma unroll
                for (int n4 = 0; n4 < 4; n4++) {
                    float acc[4] = {0.f, 0.f, 0.f, 0.f};
#pragma unroll
                    for (int kt = 0; kt < 4; kt++) {
                        mma16816(acc, Ah[kt], Bh0[n4][kt], Bh1[n4][kt]);
                        mma16816(acc, Ah[kt], Bl0[n4][kt], Bl1[n4][kt]);
                        mma16816(acc, Al[kt], Bh0[n4][kt], Bh1[n4][kt]);
                    }
                    int col = (ws * 4 + n4) * 8 + 2 * tig;
                    size_t row0 = (size_t)b * TSTEPS + r0 + gid;
                    *(float2*)(g_xg2 + row0 * G4 + col) =
                        make_float2(acc[0] + bias0[n4], acc[1] + bias1[n4]);
                    *(float2*)(g_xg2 + (row0 + 8) * G4 + col) =
                        make_float2(acc[2] + bias0[n4], acc[3] + bias1[n4]);
                }
            };

            for (int t = 0; t < TSTEPS; t++) {
                if (t > 0 && (t & 15) == 0) do_chunk(t - 16);
                __syncthreads();
                // Publish AFTER the block barrier: all GEMM warps' stores
                // happen-before this point; release carries that history.
                if (tid == 256 && t > 0 && (t & 15) == 0) {
                    __threadfence();
                    st_rel(&g_flag[b], (unsigned)t);       // rows 0..t-1 ready
                }
            }
            do_chunk(TSTEPS - 16);                         // final chunk
            __syncthreads();                               // post (rec matches)
            if (tid == 256) {
                __threadfence();
                st_rel(&g_flag[b], (unsigned)TSTEPS);
            }
        }
    } else {
        // ======== consumer: layer2 recurrence (PLAIN coherent loads) ========
        if (w < 8) {
            int gt = lane >> 3;
            int u  = (w << 3) + (lane & 7);
            int gidx = gt * 64 + u;
            ull wv[32];
#pragma unroll
            for (int k = 0; k < 32; k++)
                wv[k] = pack64(__ldg(Whh2 + (size_t)gidx * 64 + 2 * k),
                               __ldg(Whh2 + (size_t)gidx * 64 + 2 * k + 1));
            float mval = (lane < 8) ? __ldg(mask2 + b * 64 + u) : 0.0f;
            if (tid < 64) { hq[0][tid] = 0.0f; hq[1][tid] = 0.0f; }
            float c = 0.0f;
            const float* xgp = g_xg2 + (size_t)b * TSTEPS * G4 + gidx;
            unsigned avail = 0;
            __syncthreads();                               // bar0
            while (avail < 4u) { avail = ld_acq(&g_flag[b]); if (avail < 4u) __nanosleep(64); }
            float x0 = xgp[0];
            float x1 = xgp[G4];
            float x2 = xgp[2 * G4];
            float x3 = xgp[3 * G4];
            for (int t = 0; t < TSTEPS; t++) {
                int cur = t & 1;
                float xc = x0; x0 = x1; x1 = x2; x2 = x3;
                if (t + 4 < TSTEPS) {
                    unsigned need = (unsigned)(t + 5);
                    while (avail < need) { avail = ld_acq(&g_flag[b]); if (avail < need) __nanosleep(64); }
                    x3 = xgp[(size_t)(t + 4) * G4];
                }
                float pre = dot32p(hq[cur], wv) + xc;
                float A = (gt == 2) ? tanh_mufu(pre) : sig_mufu(pre);
                float fA = __shfl_xor_sync(0xffffffffu, A, 8);
                float gA = __shfl_xor_sync(0xffffffffu, A, 16);
                float oA = __shfl_xor_sync(0xffffffffu, A, 24);
                if (lane < 8) {
                    c = fA * c + A * gA;
                    float h = oA * tanh_mufu(c);
                    hq[cur ^ 1][u] = h;
                    out[((size_t)b * TSTEPS + t) * HID + u] = fmaxf(h * mval, 0.0f);
                }
                __syncthreads();
            }
        } else {
            // exact barrier-matching loop (bar0 + TSTEPS)
            __syncthreads();
            for (int t = 0; t < TSTEPS; t++) __syncthreads();
        }
    }
}

// ---------------------------------------------------------------------------
// Launch
// ---------------------------------------------------------------------------
extern "C" void kernel_launch(void* const* d_in, const int* in_sizes, int n_in,
                              void* d_out, int out_size) {
    const float* x     = (const float*)d_in[0];
    const float* W_ih1 = (const float*)d_in[1];
    const float* W_hh1 = (const float*)d_in[2];
    const float* b_ih1 = (const float*)d_in[3];
    const float* b_hh1 = (const float*)d_in[4];
    const float* W_ih2 = (const float*)d_in[5];
    const float* W_hh2 = (const float*)d_in[6];
    const float* b_ih2 = (const float*)d_in[7];
    const float* b_hh2 = (const float*)d_in[8];
    const float* mask1 = (const float*)d_in[9];
    const float* mask2 = (const float*)d_in[10];
    float* out = (float*)d_out;

    prep_x_kernel<<<(M_ROWS * 64) / 256, 256>>>(x);
    prep_w_kernel<<<(32 * 8 * 32 + 127) / 128, 128>>>(W_ih1);
    gemm_kernel<<<dim3(M_ROWS / 64, 2), 256>>>(b_ih1, b_hh1);
    fused_kernel<<<2 * BATCH, 512>>>(W_hh1, mask1, W_ih2, b_ih2, b_hh2,
                                     W_hh2, mask2, out);
}

// round 12
// speedup vs baseline: 1.5511x; 1.2042x over previous
#include <cuda_runtime.h>
#include <cuda_bf16.h>
#include <cstdint>

#define BATCH  64
#define TSTEPS 2048
#define M_ROWS (BATCH * TSTEPS)   // 131072
#define HID    64
#define G4     256

typedef unsigned long long ull;

// ---------------------------------------------------------------------------
// Scratch
// ---------------------------------------------------------------------------
__device__ float    g_xg1[(size_t)M_ROWS * G4];   // layer1 preacts, PAIR layout
__device__ float    g_xg2[(size_t)M_ROWS * G4];   // layer2 preacts, PAIR layout
__device__ uint32_t g_xph[(size_t)M_ROWS * 64];   // x packed bf16x2 (hi)
__device__ uint32_t g_xpl[(size_t)M_ROWS * 64];   // x packed bf16x2 (lo residual)
__device__ uint4    g_wf1[32 * 8 * 32];           // W_ih1 fragment-ordered (hi+lo)
__device__ unsigned g_flag[BATCH];                // xg2 rows ready per sequence

// PAIR layout: 128 ull/row; slot s<64 = {i_s, f_s}; slot 64+s = {g_s, o_s}.

// ---------------------------------------------------------------------------
// Helpers
// ---------------------------------------------------------------------------
__device__ __forceinline__ uint32_t packbf(float lo, float hi) {
    uint32_t r;
    asm("cvt.rn.bf16x2.f32 %0, %1, %2;" : "=r"(r) : "f"(hi), "f"(lo));
    return r;
}
__device__ __forceinline__ ull pack64(float lo, float hi) {
    ull r; asm("mov.b64 %0, {%1, %2};" : "=l"(r) : "f"(lo), "f"(hi)); return r;
}
__device__ __forceinline__ void unpack64(ull v, float& lo, float& hi) {
    asm("mov.b64 {%0, %1}, %2;" : "=f"(lo), "=f"(hi) : "l"(v));
}
__device__ __forceinline__ void fma2(ull& acc, ull a, ull b) {
    asm("fma.rn.f32x2 %0, %1, %2, %0;" : "+l"(acc) : "l"(a), "l"(b));
}
__device__ __forceinline__ ull add2(ull a, ull b) {
    ull r; asm("add.rn.f32x2 %0, %1, %2;" : "=l"(r) : "l"(a), "l"(b)); return r;
}
__device__ __forceinline__ float bf16_round(float f) {
    return __bfloat162float(__float2bfloat16_rn(f));
}
__device__ __forceinline__ float tanh_mufu(float x) {
    float y; asm("tanh.approx.f32 %0, %1;" : "=f"(y) : "f"(x)); return y;
}
__device__ __forceinline__ float sig_mufu(float x) {
    return fmaf(tanh_mufu(x * 0.5f), 0.5f, 0.5f);
}
__device__ __forceinline__ void mma16816(float* c, const uint32_t* a,
                                         uint32_t b0, uint32_t b1) {
    asm("mma.sync.aligned.m16n8k16.row.col.f32.bf16.bf16.f32 "
        "{%0,%1,%2,%3}, {%4,%5,%6,%7}, {%8,%9}, {%0,%1,%2,%3};"
        : "+f"(c[0]), "+f"(c[1]), "+f"(c[2]), "+f"(c[3])
        : "r"(a[0]), "r"(a[1]), "r"(a[2]), "r"(a[3]), "r"(b0), "r"(b1));
}
__device__ __forceinline__ unsigned ld_acq(const unsigned* p) {
    unsigned v;
    asm volatile("ld.acquire.gpu.global.u32 %0, [%1];" : "=r"(v) : "l"(p) : "memory");
    return v;
}
__device__ __forceinline__ void st_rel(unsigned* p, unsigned v) {
    asm volatile("st.release.gpu.global.u32 [%0], %1;" :: "l"(p), "r"(v) : "memory");
}
__device__ __forceinline__ void bar_rec() {          // rec-warps-only barrier
    asm volatile("bar.sync 1, 128;" ::: "memory");
}

// 64-pair packed dot, software-pipelined: double-buffered chunks of 4 LDS.128.
__device__ __forceinline__ ull dot64p(const ull* hp_, const ull* wv) {
    const ulonglong2* hp = (const ulonglong2*)hp_;
    ulonglong2 bufA[4], bufB[4];
#pragma unroll
    for (int i = 0; i < 4; i++) bufA[i] = hp[i];
    ull a0 = 0ull, a1 = 0ull, a2 = 0ull, a3 = 0ull;
#pragma unroll
    for (int c = 0; c < 8; c++) {
        ulonglong2* cur = (c & 1) ? bufB : bufA;
        ulonglong2* nxt = (c & 1) ? bufA : bufB;
        if (c < 7) {
#pragma unroll
            for (int i = 0; i < 4; i++) nxt[i] = hp[(c + 1) * 4 + i];
        }
        fma2(a0, cur[0].x, wv[c * 8 + 0]);
        fma2(a1, cur[0].y, wv[c * 8 + 1]);
        fma2(a2, cur[1].x, wv[c * 8 + 2]);
        fma2(a3, cur[1].y, wv[c * 8 + 3]);
        fma2(a0, cur[2].x, wv[c * 8 + 4]);
        fma2(a1, cur[2].y, wv[c * 8 + 5]);
        fma2(a2, cur[3].x, wv[c * 8 + 6]);
        fma2(a3, cur[3].y, wv[c * 8 + 7]);
    }
    return add2(add2(a0, a1), add2(a2, a3));
}

// ---------------------------------------------------------------------------
// Prep kernels
// ---------------------------------------------------------------------------
__global__ void prep_x_kernel(const float* __restrict__ x) {
    int i = blockIdx.x * blockDim.x + threadIdx.x;
    if (i < BATCH) g_flag[i] = 0;
    if (i >= M_ROWS * 64) return;
    float2 f = ((const float2*)x)[i];
    float hx = bf16_round(f.x), hy = bf16_round(f.y);
    g_xph[i] = packbf(f.x, f.y);
    g_xpl[i] = packbf(f.x - hx, f.y - hy);
}

__global__ void prep_w_kernel(const float* __restrict__ W) {
    const int KI = 8, K = 128;
    int total = 32 * KI * 32;
    int i = blockIdx.x * blockDim.x + threadIdx.x;
    if (i >= total) return;
    int lane = i & 31;
    int ki   = (i >> 5) % KI;
    int nt   = i / (32 * KI);
    int tig = lane & 3, gid = lane >> 2;
    int n  = nt * 8 + gid;
    int k0 = ki * 16 + tig * 2;
    const float* Wn = W + (size_t)n * K;
    float w00 = Wn[k0],     w01 = Wn[k0 + 1];
    float w10 = Wn[k0 + 8], w11 = Wn[k0 + 9];
    uint4 v;
    v.x = packbf(w00, w01);
    v.y = packbf(w10, w11);
    v.z = packbf(w00 - bf16_round(w00), w01 - bf16_round(w01));
    v.w = packbf(w10 - bf16_round(w10), w11 - bf16_round(w11));
    g_wf1[(nt * KI + ki) * 32 + lane] = v;
}

// ---------------------------------------------------------------------------
// GEMM1: g_xg1 = x @ W_ih1^T + bias (3-term bf16 split), PAIR-layout epilogue.
// ---------------------------------------------------------------------------
__device__ __forceinline__ void st_pair(float* base, size_t r, int c, float v) {
    int slot = (c & 63) + ((c & 128) ? 64 : 0);
    int e    = (c >> 6) & 1;
    base[r * G4 + slot * 2 + e] = v;
}

__global__ __launch_bounds__(256, 2) void gemm_kernel(
    const float* __restrict__ bias_a, const float* __restrict__ bias_b)
{
    const int KI = 8, PPR = 64;
    int tid = threadIdx.x;
    int lane = tid & 31, wid = tid >> 5;
    int tig = lane & 3, gid = lane >> 2;
    int wm = wid & 3, wn = wid >> 2;
    int rb = blockIdx.x * 64 + wm * 16;
    int ntBase = (blockIdx.y * 2 + wn) * 8;

    float acc[8][4];
#pragma unroll
    for (int j = 0; j < 8; j++)
#pragma unroll
        for (int q = 0; q < 4; q++) acc[j][q] = 0.0f;

#pragma unroll
    for (int ki = 0; ki < KI; ki++) {
        uint32_t a[4], al[4];
        size_t r0 = (size_t)(rb + gid) * PPR + ki * 8;
        a[0]  = __ldg(g_xph + r0 + tig);
        a[1]  = __ldg(g_xph + r0 + 8 * PPR + tig);
        a[2]  = __ldg(g_xph + r0 + 4 + tig);
        a[3]  = __ldg(g_xph + r0 + 8 * PPR + 4 + tig);
        al[0] = __ldg(g_xpl + r0 + tig);
        al[1] = __ldg(g_xpl + r0 + 8 * PPR + tig);
        al[2] = __ldg(g_xpl + r0 + 4 + tig);
        al[3] = __ldg(g_xpl + r0 + 8 * PPR + 4 + tig);
#pragma unroll
        for (int j = 0; j < 8; j++) {
            uint4 bf = __ldg(&g_wf1[((ntBase + j) * KI + ki) * 32 + lane]);
            mma16816(acc[j], a,  bf.x, bf.y);
            mma16816(acc[j], a,  bf.z, bf.w);
            mma16816(acc[j], al, bf.x, bf.y);
        }
    }

#pragma unroll
    for (int j = 0; j < 8; j++) {
        int nc = (ntBase + j) * 8 + tig * 2;
        float bs0 = __ldg(bias_a + nc) + __ldg(bias_b + nc);
        float bs1 = __ldg(bias_a + nc + 1) + __ldg(bias_b + nc + 1);
        size_t r = (size_t)(rb + gid);
        st_pair(g_xg1, r,     nc,     acc[j][0] + bs0);
        st_pair(g_xg1, r,     nc + 1, acc[j][1] + bs1);
        st_pair(g_xg1, r + 8, nc,     acc[j][2] + bs0);
        st_pair(g_xg1, r + 8, nc + 1, acc[j][3] + bs1);
    }
}

// ---------------------------------------------------------------------------
// Fused co-resident kernel: 128 CTAs x 256 threads (single wave).
//  PRODUCER (b<64):
//   warps 0-3: layer1 rec, 2 gates packed/thread (R4 body), h in an 8-deep
//     ring; per-step rec-only barrier (bar.sync 1,128); joint __syncthreads
//     every 4 steps.
//   warps 4-7: GEMV batch of 4 xg2 rows per joint barrier (overlaps rec),
//     mask1 folded into weights; publish flag after joint barrier.
//  CONSUMER (b>=64): warps 0-3 layer2 rec on PLAIN loads of g_xg2, gated by
//     g_flag; warps 4-7 exit.
// ---------------------------------------------------------------------------
__global__ __launch_bounds__(256, 1) void fused_kernel(
    const float* __restrict__ Whh1, const float* __restrict__ mask1,
    const float* __restrict__ Wih2, const float* __restrict__ bih2,
    const float* __restrict__ bhh2,
    const float* __restrict__ Whh2, const float* __restrict__ mask2,
    float* __restrict__ out)
{
    __shared__ alignas(16) ull ring[8][64];   // h history: row t at ring[t&7]

    int tid = threadIdx.x;
    bool producer = blockIdx.x < BATCH;
    int b = producer ? blockIdx.x : blockIdx.x - BATCH;
    int lane = tid & 31, w = tid >> 5;

    if (producer) {
        if (w < 4) {
            // ======== layer1 recurrence (R4 2-gate packed body) ========
            int jj = (w << 4) + (lane & 15);
            bool isIF = lane < 16;
            int rA = isIF ? jj : 128 + jj;
            ull wv[64];
#pragma unroll
            for (int k = 0; k < 64; k++)
                wv[k] = pack64(__ldg(Whh1 + (size_t)rA * 64 + k),
                               __ldg(Whh1 + (size_t)(rA + 64) * 64 + k));
            if (tid < 64) ring[7][tid] = 0ull;             // h(-1) = 0
            float c = 0.0f;
            const ull* xgb = (const ull*)g_xg1 + (size_t)b * TSTEPS * 128
                             + (isIF ? jj : 64 + jj);
            bar_rec();                                     // ring init visible
            ull x0 = __ldg(xgb);
            ull x1 = __ldg(xgb + 128);
            ull x2 = __ldg(xgb + 2 * 128);
            ull x3 = __ldg(xgb + 3 * 128);
            for (int t = 0; t < TSTEPS; t++) {
                ull xc = x0; x0 = x1; x1 = x2; x2 = x3;
                if (t + 4 < TSTEPS) x3 = __ldg(xgb + (size_t)(t + 4) * 128);
                ull s = add2(dot64p(ring[(t + 7) & 7], wv), xc);
                float gA, gB; unpack64(s, gA, gB);
                float A0, A1;
                if (isIF) { A0 = sig_mufu(gA);  A1 = sig_mufu(gB); }
                else      { A0 = tanh_mufu(gA); A1 = sig_mufu(gB); }
                float sg = __shfl_xor_sync(0xffffffffu, A0, 16);
                float so = __shfl_xor_sync(0xffffffffu, A1, 16);
                if (isIF) {
                    c = A1 * c + A0 * sg;
                    float h = so * tanh_mufu(c);
                    ring[t & 7][jj] = pack64(h, h);
                }
                bar_rec();                                 // rec-only, per step
                if ((t & 3) == 3) __syncthreads();         // joint, every 4
            }
            __syncthreads();                               // final joint
        } else {
            // ======== GEMV warps: 4 xg2 rows per superstep ========
            int s = tid - 128;                             // pair slot 0..127
            int rA = (s < 64) ? s : 128 + (s - 64);
            ull wxv[64];
#pragma unroll
            for (int k = 0; k < 64; k++) {
                float m = __ldg(mask1 + b * 64 + k);
                wxv[k] = pack64(__ldg(Wih2 + (size_t)rA * 64 + k) * m,
                                __ldg(Wih2 + (size_t)(rA + 64) * 64 + k) * m);
            }
            ull bias = pack64(__ldg(bih2 + rA) + __ldg(bhh2 + rA),
                              __ldg(bih2 + rA + 64) + __ldg(bhh2 + rA + 64));
            ull* dst = (ull*)g_xg2 + (size_t)b * TSTEPS * 128 + s;
            for (int kk = 1; kk <= TSTEPS / 4; kk++) {
                __syncthreads();                           // joint barrier kk
                int r0 = 4 * (kk - 1);
                // rows 0..r0-1 fully stored by ALL gemv warps before this
                // barrier; publish them.
                if (tid == 128 && r0 > 0) {
                    __threadfence();
                    st_rel(&g_flag[b], (unsigned)r0);
                }
#pragma unroll
                for (int j = 0; j < 4; j++) {
                    ull sum = add2(dot64p(ring[(r0 + j) & 7], wxv), bias);
                    dst[(size_t)(r0 + j) * 128] = sum;
                }
            }
            __syncthreads();                               // final joint
            if (tid == 128) {
                __threadfence();
                st_rel(&g_flag[b], (unsigned)TSTEPS);
            }
        }
    } else {
        // ======== consumer: layer2 recurrence ========
        if (w >= 4) return;                                // warps 4-7 exit
        int jj = (w << 4) + (lane & 15);
        bool isIF = lane < 16;
        int rA = isIF ? jj : 128 + jj;
        ull wv[64];
#pragma unroll
        for (int k = 0; k < 64; k++)
            wv[k] = pack64(__ldg(Whh2 + (size_t)rA * 64 + k),
                           __ldg(Whh2 + (size_t)(rA + 64) * 64 + k));
        float mval = isIF ? __ldg(mask2 + b * 64 + jj) : 0.0f;
        if (tid < 64) ring[7][tid] = 0ull;
        float c = 0.0f;
        const ull* xgb = (const ull*)g_xg2 + (size_t)b * TSTEPS * 128
                         + (isIF ? jj : 64 + jj);
        unsigned avail = 0;
        bar_rec();
        while (avail < 4u) { avail = ld_acq(&g_flag[b]); if (avail < 4u) __nanosleep(64); }
        ull x0 = xgb[0];                                   // PLAIN loads
        ull x1 = xgb[128];
        ull x2 = xgb[2 * 128];
        ull x3 = xgb[3 * 128];
        for (int t = 0; t < TSTEPS; t++) {
            ull xc = x0; x0 = x1; x1 = x2; x2 = x3;
            if (t + 4 < TSTEPS) {
                unsigned need = (unsigned)(t + 5);
                while (avail < need) { avail = ld_acq(&g_flag[b]); if (avail < need) __nanosleep(64); }
                x3 = xgb[(size_t)(t + 4) * 128];
            }
            ull sv = add2(dot64p(ring[(t + 7) & 7], wv), xc);
            float gA, gB; unpack64(sv, gA, gB);
            float A0, A1;
            if (isIF) { A0 = sig_mufu(gA);  A1 = sig_mufu(gB); }
            else      { A0 = tanh_mufu(gA); A1 = sig_mufu(gB); }
            float sg = __shfl_xor_sync(0xffffffffu, A0, 16);
            float so = __shfl_xor_sync(0xffffffffu, A1, 16);
            if (isIF) {
                c = A1 * c + A0 * sg;
                float h = so * tanh_mufu(c);
                ring[t & 7][jj] = pack64(h, h);
                out[((size_t)b * TSTEPS + t) * HID + jj] = fmaxf(h * mval, 0.0f);
            }
            bar_rec();
        }
    }
}

// ---------------------------------------------------------------------------
// Launch
// ---------------------------------------------------------------------------
extern "C" void kernel_launch(void* const* d_in, const int* in_sizes, int n_in,
                              void* d_out, int out_size) {
    const float* x     = (const float*)d_in[0];
    const float* W_ih1 = (const float*)d_in[1];
    const float* W_hh1 = (const float*)d_in[2];
    const float* b_ih1 = (const float*)d_in[3];
    const float* b_hh1 = (const float*)d_in[4];
    const float* W_ih2 = (const float*)d_in[5];
    const float* W_hh2 = (const float*)d_in[6];
    const float* b_ih2 = (const float*)d_in[7];
    const float* b_hh2 = (const float*)d_in[8];
    const float* mask1 = (const float*)d_in[9];
    const float* mask2 = (const float*)d_in[10];
    float* out = (float*)d_out;

    prep_x_kernel<<<(M_ROWS * 64) / 256, 256>>>(x);
    prep_w_kernel<<<(32 * 8 * 32 + 127) / 128, 128>>>(W_ih1);
    gemm_kernel<<<dim3(M_ROWS / 64, 2), 256>>>(b_ih1, b_hh1);
    fused_kernel<<<2 * BATCH, 256>>>(W_hh1, mask1, W_ih2, b_ih2, b_hh2,
                                     W_hh2, mask2, out);
}

// round 13
// speedup vs baseline: 1.7852x; 1.1509x over previous
#include <cuda_runtime.h>
#include <cuda_bf16.h>
#include <cstdint>

#define BATCH  64
#define TSTEPS 2048
#define M_ROWS (BATCH * TSTEPS)   // 131072
#define HID    64
#define G4     256

typedef unsigned long long ull;

// ---------------------------------------------------------------------------
// Scratch
// ---------------------------------------------------------------------------
__device__ float    g_xg1[(size_t)M_ROWS * G4];   // layer1 preacts, PAIR layout
__device__ float    g_xg2[(size_t)M_ROWS * G4];   // layer2 preacts, PAIR layout
__device__ uint32_t g_xph[(size_t)M_ROWS * 64];   // x packed bf16x2 (hi)
__device__ uint32_t g_xpl[(size_t)M_ROWS * 64];   // x packed bf16x2 (lo residual)
__device__ uint4    g_wf1[32 * 8 * 32];           // W_ih1 fragment-ordered (hi+lo)
__device__ unsigned g_flag[BATCH];                // xg2 rows ready per sequence

// PAIR layout: 128 ull/row; slot s<64 = {i_s, f_s}; slot 64+s = {g_s, o_s}.

// ---------------------------------------------------------------------------
// Helpers
// ---------------------------------------------------------------------------
__device__ __forceinline__ uint32_t packbf(float lo, float hi) {
    uint32_t r;
    asm("cvt.rn.bf16x2.f32 %0, %1, %2;" : "=r"(r) : "f"(hi), "f"(lo));
    return r;
}
__device__ __forceinline__ ull pack64(float lo, float hi) {
    ull r; asm("mov.b64 %0, {%1, %2};" : "=l"(r) : "f"(lo), "f"(hi)); return r;
}
__device__ __forceinline__ void unpack64(ull v, float& lo, float& hi) {
    asm("mov.b64 {%0, %1}, %2;" : "=f"(lo), "=f"(hi) : "l"(v));
}
__device__ __forceinline__ void fma2(ull& acc, ull a, ull b) {
    asm("fma.rn.f32x2 %0, %1, %2, %0;" : "+l"(acc) : "l"(a), "l"(b));
}
__device__ __forceinline__ ull add2(ull a, ull b) {
    ull r; asm("add.rn.f32x2 %0, %1, %2;" : "=l"(r) : "l"(a), "l"(b)); return r;
}
__device__ __forceinline__ float bf16_round(float f) {
    return __bfloat162float(__float2bfloat16_rn(f));
}
__device__ __forceinline__ float tanh_mufu(float x) {
    float y; asm("tanh.approx.f32 %0, %1;" : "=f"(y) : "f"(x)); return y;
}
__device__ __forceinline__ float sig_mufu(float x) {
    return fmaf(tanh_mufu(x * 0.5f), 0.5f, 0.5f);
}
__device__ __forceinline__ void mma16816(float* c, const uint32_t* a,
                                         uint32_t b0, uint32_t b1) {
    asm("mma.sync.aligned.m16n8k16.row.col.f32.bf16.bf16.f32 "
        "{%0,%1,%2,%3}, {%4,%5,%6,%7}, {%8,%9}, {%0,%1,%2,%3};"
        : "+f"(c[0]), "+f"(c[1]), "+f"(c[2]), "+f"(c[3])
        : "r"(a[0]), "r"(a[1]), "r"(a[2]), "r"(a[3]), "r"(b0), "r"(b1));
}
__device__ __forceinline__ unsigned ld_acq(const unsigned* p) {
    unsigned v;
    asm volatile("ld.acquire.gpu.global.u32 %0, [%1];" : "=r"(v) : "l"(p) : "memory");
    return v;
}
__device__ __forceinline__ void st_rel(unsigned* p, unsigned v) {
    asm volatile("st.release.gpu.global.u32 [%0], %1;" :: "l"(p), "r"(v) : "memory");
}
__device__ __forceinline__ void bar_rec() {          // rec-warps-only barrier
    asm volatile("bar.sync 1, 128;" ::: "memory");
}

// 64-pair packed dot, software-pipelined: double-buffered chunks of 4 LDS.128.
__device__ __forceinline__ ull dot64p(const ull* hp_, const ull* wv) {
    const ulonglong2* hp = (const ulonglong2*)hp_;
    ulonglong2 bufA[4], bufB[4];
#pragma unroll
    for (int i = 0; i < 4; i++) bufA[i] = hp[i];
    ull a0 = 0ull, a1 = 0ull, a2 = 0ull, a3 = 0ull;
#pragma unroll
    for (int c = 0; c < 8; c++) {
        ulonglong2* cur = (c & 1) ? bufB : bufA;
        ulonglong2* nxt = (c & 1) ? bufA : bufB;
        if (c < 7) {
#pragma unroll
            for (int i = 0; i < 4; i++) nxt[i] = hp[(c + 1) * 4 + i];
        }
        fma2(a0, cur[0].x, wv[c * 8 + 0]);
        fma2(a1, cur[0].y, wv[c * 8 + 1]);
        fma2(a2, cur[1].x, wv[c * 8 + 2]);
        fma2(a3, cur[1].y, wv[c * 8 + 3]);
        fma2(a0, cur[2].x, wv[c * 8 + 4]);
        fma2(a1, cur[2].y, wv[c * 8 + 5]);
        fma2(a2, cur[3].x, wv[c * 8 + 6]);
        fma2(a3, cur[3].y, wv[c * 8 + 7]);
    }
    return add2(add2(a0, a1), add2(a2, a3));
}

// ---------------------------------------------------------------------------
// Prep kernels
// ---------------------------------------------------------------------------
__global__ void prep_x_kernel(const float* __restrict__ x) {
    int i = blockIdx.x * blockDim.x + threadIdx.x;
    if (i < BATCH) g_flag[i] = 0;
    if (i >= M_ROWS * 64) return;
    float2 f = ((const float2*)x)[i];
    float hx = bf16_round(f.x), hy = bf16_round(f.y);
    g_xph[i] = packbf(f.x, f.y);
    g_xpl[i] = packbf(f.x - hx, f.y - hy);
}

__global__ void prep_w_kernel(const float* __restrict__ W) {
    const int KI = 8, K = 128;
    int total = 32 * KI * 32;
    int i = blockIdx.x * blockDim.x + threadIdx.x;
    if (i >= total) return;
    int lane = i & 31;
    int ki   = (i >> 5) % KI;
    int nt   = i / (32 * KI);
    int tig = lane & 3, gid = lane >> 2;
    int n  = nt * 8 + gid;
    int k0 = ki * 16 + tig * 2;
    const float* Wn = W + (size_t)n * K;
    float w00 = Wn[k0],     w01 = Wn[k0 + 1];
    float w10 = Wn[k0 + 8], w11 = Wn[k0 + 9];
    uint4 v;
    v.x = packbf(w00, w01);
    v.y = packbf(w10, w11);
    v.z = packbf(w00 - bf16_round(w00), w01 - bf16_round(w01));
    v.w = packbf(w10 - bf16_round(w10), w11 - bf16_round(w11));
    g_wf1[(nt * KI + ki) * 32 + lane] = v;
}

// ---------------------------------------------------------------------------
// GEMM1: g_xg1 = x @ W_ih1^T + bias (3-term bf16 split), PAIR-layout epilogue.
// ---------------------------------------------------------------------------
__device__ __forceinline__ void st_pair(float* base, size_t r, int c, float v) {
    int slot = (c & 63) + ((c & 128) ? 64 : 0);
    int e    = (c >> 6) & 1;
    base[r * G4 + slot * 2 + e] = v;
}

__global__ __launch_bounds__(256, 2) void gemm_kernel(
    const float* __restrict__ bias_a, const float* __restrict__ bias_b)
{
    const int KI = 8, PPR = 64;
    int tid = threadIdx.x;
    int lane = tid & 31, wid = tid >> 5;
    int tig = lane & 3, gid = lane >> 2;
    int wm = wid & 3, wn = wid >> 2;
    int rb = blockIdx.x * 64 + wm * 16;
    int ntBase = (blockIdx.y * 2 + wn) * 8;

    float acc[8][4];
#pragma unroll
    for (int j = 0; j < 8; j++)
#pragma unroll
        for (int q = 0; q < 4; q++) acc[j][q] = 0.0f;

#pragma unroll
    for (int ki = 0; ki < KI; ki++) {
        uint32_t a[4], al[4];
        size_t r0 = (size_t)(rb + gid) * PPR + ki * 8;
        a[0]  = __ldg(g_xph + r0 + tig);
        a[1]  = __ldg(g_xph + r0 + 8 * PPR + tig);
        a[2]  = __ldg(g_xph + r0 + 4 + tig);
        a[3]  = __ldg(g_xph + r0 + 8 * PPR + 4 + tig);
        al[0] = __ldg(g_xpl + r0 + tig);
        al[1] = __ldg(g_xpl + r0 + 8 * PPR + tig);
        al[2] = __ldg(g_xpl + r0 + 4 + tig);
        al[3] = __ldg(g_xpl + r0 + 8 * PPR + 4 + tig);
#pragma unroll
        for (int j = 0; j < 8; j++) {
            uint4 bf = __ldg(&g_wf1[((ntBase + j) * KI + ki) * 32 + lane]);
            mma16816(acc[j], a,  bf.x, bf.y);
            mma16816(acc[j], a,  bf.z, bf.w);
            mma16816(acc[j], al, bf.x, bf.y);
        }
    }

#pragma unroll
    for (int j = 0; j < 8; j++) {
        int nc = (ntBase + j) * 8 + tig * 2;
        float bs0 = __ldg(bias_a + nc) + __ldg(bias_b + nc);
        float bs1 = __ldg(bias_a + nc + 1) + __ldg(bias_b + nc + 1);
        size_t r = (size_t)(rb + gid);
        st_pair(g_xg1, r,     nc,     acc[j][0] + bs0);
        st_pair(g_xg1, r,     nc + 1, acc[j][1] + bs1);
        st_pair(g_xg1, r + 8, nc,     acc[j][2] + bs0);
        st_pair(g_xg1, r + 8, nc + 1, acc[j][3] + bs1);
    }
}

// ---------------------------------------------------------------------------
// Fused co-resident kernel: 128 CTAs x 256 threads (single wave).
// R11 structure; the change this round is TRUE distance-4 prefetch:
// the time loop is unrolled x4 and phase p's register xr[p] is reloaded for
// t+4 right after consumption (previous rotation scheme had an effective
// reuse distance of ONE step, exposing DRAM latency every step).
// Consumer additionally polls the flag once per 4-step group.
// ---------------------------------------------------------------------------
__global__ __launch_bounds__(256, 1) void fused_kernel(
    const float* __restrict__ Whh1, const float* __restrict__ mask1,
    const float* __restrict__ Wih2, const float* __restrict__ bih2,
    const float* __restrict__ bhh2,
    const float* __restrict__ Whh2, const float* __restrict__ mask2,
    float* __restrict__ out)
{
    __shared__ alignas(16) ull ring[8][64];   // h history: row t at ring[t&7]

    int tid = threadIdx.x;
    bool producer = blockIdx.x < BATCH;
    int b = producer ? blockIdx.x : blockIdx.x - BATCH;
    int lane = tid & 31, w = tid >> 5;

    if (producer) {
        if (w < 4) {
            // ======== layer1 recurrence, unrolled x4 ========
            int jj = (w << 4) + (lane & 15);
            bool isIF = lane < 16;
            int rA = isIF ? jj : 128 + jj;
            ull wv[64];
#pragma unroll
            for (int k = 0; k < 64; k++)
                wv[k] = pack64(__ldg(Whh1 + (size_t)rA * 64 + k),
                               __ldg(Whh1 + (size_t)(rA + 64) * 64 + k));
            if (tid < 64) ring[7][tid] = 0ull;             // h(-1) = 0
            float c = 0.0f;
            const ull* xgb = (const ull*)g_xg1 + (size_t)b * TSTEPS * 128
                             + (isIF ? jj : 64 + jj);
            bar_rec();                                     // ring init visible
            ull xr[4];
#pragma unroll
            for (int p = 0; p < 4; p++) xr[p] = __ldg(xgb + (size_t)p * 128);
            for (int t0 = 0; t0 < TSTEPS; t0 += 4) {
#pragma unroll
                for (int p = 0; p < 4; p++) {
                    int t = t0 + p;
                    ull xc = xr[p];
                    if (t + 4 < TSTEPS)                     // reload: used at t+4
                        xr[p] = __ldg(xgb + (size_t)(t + 4) * 128);
                    ull s = add2(dot64p(ring[(t + 7) & 7], wv), xc);
                    float gA, gB; unpack64(s, gA, gB);
                    float A0, A1;
                    if (isIF) { A0 = sig_mufu(gA);  A1 = sig_mufu(gB); }
                    else      { A0 = tanh_mufu(gA); A1 = sig_mufu(gB); }
                    float sg = __shfl_xor_sync(0xffffffffu, A0, 16);
                    float so = __shfl_xor_sync(0xffffffffu, A1, 16);
                    if (isIF) {
                        c = A1 * c + A0 * sg;
                        float h = so * tanh_mufu(c);
                        ring[t & 7][jj] = pack64(h, h);
                    }
                    bar_rec();                              // rec-only, per step
                }
                __syncthreads();                            // joint, every 4
            }
            __syncthreads();                                // final joint
        } else {
            // ======== GEMV warps: 4 xg2 rows per superstep ========
            int s = tid - 128;                              // pair slot 0..127
            int rA = (s < 64) ? s : 128 + (s - 64);
            ull wxv[64];
#pragma unroll
            for (int k = 0; k < 64; k++) {
                float m = __ldg(mask1 + b * 64 + k);
                wxv[k] = pack64(__ldg(Wih2 + (size_t)rA * 64 + k) * m,
                                __ldg(Wih2 + (size_t)(rA + 64) * 64 + k) * m);
            }
            ull bias = pack64(__ldg(bih2 + rA) + __ldg(bhh2 + rA),
                              __ldg(bih2 + rA + 64) + __ldg(bhh2 + rA + 64));
            ull* dst = (ull*)g_xg2 + (size_t)b * TSTEPS * 128 + s;
            for (int kk = 1; kk <= TSTEPS / 4; kk++) {
                __syncthreads();                            // joint barrier kk
                int r0 = 4 * (kk - 1);
                if (tid == 128 && r0 > 0) {
                    __threadfence();
                    st_rel(&g_flag[b], (unsigned)r0);       // rows 0..r0-1 ready
                }
#pragma unroll
                for (int j = 0; j < 4; j++) {
                    ull sum = add2(dot64p(ring[(r0 + j) & 7], wxv), bias);
                    dst[(size_t)(r0 + j) * 128] = sum;
                }
            }
            __syncthreads();                                // final joint
            if (tid == 128) {
                __threadfence();
                st_rel(&g_flag[b], (unsigned)TSTEPS);
            }
        }
    } else {
        // ======== consumer: layer2 recurrence, unrolled x4 ========
        if (w >= 4) return;                                 // warps 4-7 exit
        int jj = (w << 4) + (lane & 15);
        bool isIF = lane < 16;
        int rA = isIF ? jj : 128 + jj;
        ull wv[64];
#pragma unroll
        for (int k = 0; k < 64; k++)
            wv[k] = pack64(__ldg(Whh2 + (size_t)rA * 64 + k),
                           __ldg(Whh2 + (size_t)(rA + 64) * 64 + k));
        float mval = isIF ? __ldg(mask2 + b * 64 + jj) : 0.0f;
        if (tid < 64) ring[7][tid] = 0ull;
        float c = 0.0f;
        const ull* xgb = (const ull*)g_xg2 + (size_t)b * TSTEPS * 128
                         + (isIF ? jj : 64 + jj);
        unsigned avail = 0;
        bar_rec();
        while (avail < 4u) { avail = ld_acq(&g_flag[b]); if (avail < 4u) __nanosleep(64); }
        ull xr[4];
#pragma unroll
        for (int p = 0; p < 4; p++) xr[p] = xgb[(size_t)p * 128];  // PLAIN loads
        for (int t0 = 0; t0 < TSTEPS; t0 += 4) {
            if (t0 + 4 < TSTEPS) {
                unsigned need = (unsigned)(t0 + 8 > TSTEPS ? TSTEPS : t0 + 8);
                while (avail < need) { avail = ld_acq(&g_flag[b]); if (avail < need) __nanosleep(64); }
            }
#pragma unroll
            for (int p = 0; p < 4; p++) {
                int t = t0 + p;
                ull xc = xr[p];
                if (t + 4 < TSTEPS)
                    xr[p] = xgb[(size_t)(t + 4) * 128];     // PLAIN load
                ull sv = add2(dot64p(ring[(t + 7) & 7], wv), xc);
                float gA, gB; unpack64(sv, gA, gB);
                float A0, A1;
                if (isIF) { A0 = sig_mufu(gA);  A1 = sig_mufu(gB); }
                else      { A0 = tanh_mufu(gA); A1 = sig_mufu(gB); }
                float sg = __shfl_xor_sync(0xffffffffu, A0, 16);
                float so = __shfl_xor_sync(0xffffffffu, A1, 16);
                if (isIF) {
                    c = A1 * c + A0 * sg;
                    float h = so * tanh_mufu(c);
                    ring[t & 7][jj] = pack64(h, h);
                    out[((size_t)b * TSTEPS + t) * HID + jj] = fmaxf(h * mval, 0.0f);
                }
                bar_rec();
            }
        }
    }
}

// ---------------------------------------------------------------------------
// Launch
// ---------------------------------------------------------------------------
extern "C" void kernel_launch(void* const* d_in, const int* in_sizes, int n_in,
                              void* d_out, int out_size) {
    const float* x     = (const float*)d_in[0];
    const float* W_ih1 = (const float*)d_in[1];
    const float* W_hh1 = (const float*)d_in[2];
    const float* b_ih1 = (const float*)d_in[3];
    const float* b_hh1 = (const float*)d_in[4];
    const float* W_ih2 = (const float*)d_in[5];
    const float* W_hh2 = (const float*)d_in[6];
    const float* b_ih2 = (const float*)d_in[7];
    const float* b_hh2 = (const float*)d_in[8];
    const float* mask1 = (const float*)d_in[9];
    const float* mask2 = (const float*)d_in[10];
    float* out = (float*)d_out;

    prep_x_kernel<<<(M_ROWS * 64) / 256, 256>>>(x);
    prep_w_kernel<<<(32 * 8 * 32 + 127) / 128, 128>>>(W_ih1);
    gemm_kernel<<<dim3(M_ROWS / 64, 2), 256>>>(b_ih1, b_hh1);
    fused_kernel<<<2 * BATCH, 256>>>(W_hh1, mask1, W_ih2, b_ih2, b_hh2,
                                     W_hh2, mask2, out);
}

// round 14
// speedup vs baseline: 2.0916x; 1.1716x over previous
#include <cuda_runtime.h>
#include <cuda_bf16.h>
#include <cstdint>

#define BATCH  64
#define TSTEPS 2048
#define M_ROWS (BATCH * TSTEPS)   // 131072
#define HID    64
#define G4     256

typedef unsigned long long ull;

// ---------------------------------------------------------------------------
// Scratch
// ---------------------------------------------------------------------------
__device__ float    g_xg1[(size_t)M_ROWS * G4];   // layer1 preacts, natural layout
__device__ float    g_xg2[(size_t)M_ROWS * G4];   // layer2 preacts, natural layout
__device__ uint32_t g_xph[(size_t)M_ROWS * 64];   // x packed bf16x2 (hi)
__device__ uint32_t g_xpl[(size_t)M_ROWS * 64];   // x packed bf16x2 (lo residual)
__device__ uint4    g_wf1[32 * 8 * 32];           // W_ih1 fragment-ordered (hi+lo)
__device__ unsigned g_flag[BATCH];                // xg2 rows ready per sequence

// ---------------------------------------------------------------------------
// Helpers
// ---------------------------------------------------------------------------
__device__ __forceinline__ uint32_t packbf(float lo, float hi) {
    uint32_t r;
    asm("cvt.rn.bf16x2.f32 %0, %1, %2;" : "=r"(r) : "f"(hi), "f"(lo));
    return r;
}
__device__ __forceinline__ ull pack64(float lo, float hi) {
    ull r; asm("mov.b64 %0, {%1, %2};" : "=l"(r) : "f"(lo), "f"(hi)); return r;
}
__device__ __forceinline__ void unpack64(ull v, float& lo, float& hi) {
    asm("mov.b64 {%0, %1}, %2;" : "=f"(lo), "=f"(hi) : "l"(v));
}
__device__ __forceinline__ void fma2(ull& acc, ull a, ull b) {
    asm("fma.rn.f32x2 %0, %1, %2, %0;" : "+l"(acc) : "l"(a), "l"(b));
}
__device__ __forceinline__ ull add2(ull a, ull b) {
    ull r; asm("add.rn.f32x2 %0, %1, %2;" : "=l"(r) : "l"(a), "l"(b)); return r;
}
__device__ __forceinline__ float bf16_round(float f) {
    return __bfloat162float(__float2bfloat16_rn(f));
}
__device__ __forceinline__ float tanh_mufu(float x) {
    float y; asm("tanh.approx.f32 %0, %1;" : "=f"(y) : "f"(x)); return y;
}
__device__ __forceinline__ float sig_mufu(float x) {
    return fmaf(tanh_mufu(x * 0.5f), 0.5f, 0.5f);
}
__device__ __forceinline__ void mma16816(float* c, const uint32_t* a,
                                         uint32_t b0, uint32_t b1) {
    asm("mma.sync.aligned.m16n8k16.row.col.f32.bf16.bf16.f32 "
        "{%0,%1,%2,%3}, {%4,%5,%6,%7}, {%8,%9}, {%0,%1,%2,%3};"
        : "+f"(c[0]), "+f"(c[1]), "+f"(c[2]), "+f"(c[3])
        : "r"(a[0]), "r"(a[1]), "r"(a[2]), "r"(a[3]), "r"(b0), "r"(b1));
}
__device__ __forceinline__ unsigned ld_acq(const unsigned* p) {
    unsigned v;
    asm volatile("ld.acquire.gpu.global.u32 %0, [%1];" : "=r"(v) : "l"(p) : "memory");
    return v;
}
__device__ __forceinline__ void st_rel(unsigned* p, unsigned v) {
    asm volatile("st.release.gpu.global.u32 [%0], %1;" :: "l"(p), "r"(v) : "memory");
}
__device__ __forceinline__ void bar_rec256() {       // rec-warps-only barrier
    asm volatile("bar.sync 1, 256;" ::: "memory");
}

// 32-FFMA2 packed dot over h[64] (float smem row), software-pipelined LDS.128.
__device__ __forceinline__ float dot32p(const float* hp_, const ull* wv) {
    const ulonglong2* hp = (const ulonglong2*)hp_;   // 16 entries
    ulonglong2 bufA[4], bufB[4];
#pragma unroll
    for (int i = 0; i < 4; i++) bufA[i] = hp[i];
    ull a0 = 0ull, a1 = 0ull, a2 = 0ull, a3 = 0ull;
#pragma unroll
    for (int c = 0; c < 4; c++) {
        ulonglong2* cur = (c & 1) ? bufB : bufA;
        ulonglong2* nxt = (c & 1) ? bufA : bufB;
        if (c < 3) {
#pragma unroll
            for (int i = 0; i < 4; i++) nxt[i] = hp[(c + 1) * 4 + i];
        }
        fma2(a0, cur[0].x, wv[c * 8 + 0]);
        fma2(a1, cur[0].y, wv[c * 8 + 1]);
        fma2(a2, cur[1].x, wv[c * 8 + 2]);
        fma2(a3, cur[1].y, wv[c * 8 + 3]);
        fma2(a0, cur[2].x, wv[c * 8 + 4]);
        fma2(a1, cur[2].y, wv[c * 8 + 5]);
        fma2(a2, cur[3].x, wv[c * 8 + 6]);
        fma2(a3, cur[3].y, wv[c * 8 + 7]);
    }
    ull s = add2(add2(a0, a1), add2(a2, a3));
    float lo, hi; unpack64(s, lo, hi);
    return lo + hi;
}

// ---------------------------------------------------------------------------
// Prep kernels
// ---------------------------------------------------------------------------
__global__ void prep_x_kernel(const float* __restrict__ x) {
    int i = blockIdx.x * blockDim.x + threadIdx.x;
    if (i < BATCH) g_flag[i] = 0;
    if (i >= M_ROWS * 64) return;
    float2 f = ((const float2*)x)[i];
    float hx = bf16_round(f.x), hy = bf16_round(f.y);
    g_xph[i] = packbf(f.x, f.y);
    g_xpl[i] = packbf(f.x - hx, f.y - hy);
}

__global__ void prep_w_kernel(const float* __restrict__ W) {
    const int KI = 8, K = 128;
    int total = 32 * KI * 32;
    int i = blockIdx.x * blockDim.x + threadIdx.x;
    if (i >= total) return;
    int lane = i & 31;
    int ki   = (i >> 5) % KI;
    int nt   = i / (32 * KI);
    int tig = lane & 3, gid = lane >> 2;
    int n  = nt * 8 + gid;
    int k0 = ki * 16 + tig * 2;
    const float* Wn = W + (size_t)n * K;
    float w00 = Wn[k0],     w01 = Wn[k0 + 1];
    float w10 = Wn[k0 + 8], w11 = Wn[k0 + 9];
    uint4 v;
    v.x = packbf(w00, w01);
    v.y = packbf(w10, w11);
    v.z = packbf(w00 - bf16_round(w00), w01 - bf16_round(w01));
    v.w = packbf(w10 - bf16_round(w10), w11 - bf16_round(w11));
    g_wf1[(nt * KI + ki) * 32 + lane] = v;
}

// ---------------------------------------------------------------------------
// GEMM1: g_xg1 = x @ W_ih1^T + bias (3-term bf16 split), natural layout.
// ---------------------------------------------------------------------------
__global__ __launch_bounds__(256, 2) void gemm_kernel(
    const float* __restrict__ bias_a, const float* __restrict__ bias_b)
{
    const int KI = 8, PPR = 64;
    int tid = threadIdx.x;
    int lane = tid & 31, wid = tid >> 5;
    int tig = lane & 3, gid = lane >> 2;
    int wm = wid & 3, wn = wid >> 2;
    int rb = blockIdx.x * 64 + wm * 16;
    int ntBase = (blockIdx.y * 2 + wn) * 8;

    float acc[8][4];
#pragma unroll
    for (int j = 0; j < 8; j++)
#pragma unroll
        for (int q = 0; q < 4; q++) acc[j][q] = 0.0f;

#pragma unroll
    for (int ki = 0; ki < KI; ki++) {
        uint32_t a[4], al[4];
        size_t r0 = (size_t)(rb + gid) * PPR + ki * 8;
        a[0]  = __ldg(g_xph + r0 + tig);
        a[1]  = __ldg(g_xph + r0 + 8 * PPR + tig);
        a[2]  = __ldg(g_xph + r0 + 4 + tig);
        a[3]  = __ldg(g_xph + r0 + 8 * PPR + 4 + tig);
        al[0] = __ldg(g_xpl + r0 + tig);
        al[1] = __ldg(g_xpl + r0 + 8 * PPR + tig);
        al[2] = __ldg(g_xpl + r0 + 4 + tig);
        al[3] = __ldg(g_xpl + r0 + 8 * PPR + 4 + tig);
#pragma unroll
        for (int j = 0; j < 8; j++) {
            uint4 bf = __ldg(&g_wf1[((ntBase + j) * KI + ki) * 32 + lane]);
            mma16816(acc[j], a,  bf.x, bf.y);
            mma16816(acc[j], a,  bf.z, bf.w);
            mma16816(acc[j], al, bf.x, bf.y);
        }
    }

#pragma unroll
    for (int j = 0; j < 8; j++) {
        int nc = (ntBase + j) * 8 + tig * 2;
        float bs0 = __ldg(bias_a + nc) + __ldg(bias_b + nc);
        float bs1 = __ldg(bias_a + nc + 1) + __ldg(bias_b + nc + 1);
        size_t r = (size_t)(rb + gid);
        *(float2*)(g_xg1 + r * G4 + nc) =
            make_float2(acc[j][0] + bs0, acc[j][1] + bs1);
        *(float2*)(g_xg1 + (r + 8) * G4 + nc) =
            make_float2(acc[j][2] + bs0, acc[j][3] + bs1);
    }
}

// ---------------------------------------------------------------------------
// Fused co-resident kernel: 128 CTAs x 512 threads (single wave).
//  PRODUCER (b<64):
//   warps 0-7: layer1 rec, 1 gate/thread (R5-proven body, wv[32]): warp w,
//     lane l -> gate type l>>3, unit 8w+(l&7); pointwise via 3 bfly shuffles;
//     h in an 8-deep fp32 ring; rec-only bar.sync(1,256) per step; joint
//     __syncthreads every 4 steps; distance-4 phase-named xg1 prefetch.
//   warps 8-15: GEMV batch of 4 xg2 rows per joint barrier (1 gate/thread,
//     mask1 folded into weights); publish: stores -> joint barrier ->
//     tid 256 __threadfence + st.release.
//  CONSUMER (b>=64): warps 0-7 layer2 rec (same body), PLAIN coherent loads
//   of g_xg2 gated by g_flag (poll once per 4-step group); warps 8-15 exit.
// ---------------------------------------------------------------------------
__global__ __launch_bounds__(512, 1) void fused_kernel(
    const float* __restrict__ Whh1, const float* __restrict__ mask1,
    const float* __restrict__ Wih2, const float* __restrict__ bih2,
    const float* __restrict__ bhh2,
    const float* __restrict__ Whh2, const float* __restrict__ mask2,
    float* __restrict__ out)
{
    __shared__ alignas(16) float ring[8][64];   // h history: row t at ring[t&7]

    int tid = threadIdx.x;
    bool producer = blockIdx.x < BATCH;
    int b = producer ? blockIdx.x : blockIdx.x - BATCH;
    int lane = tid & 31, w = tid >> 5;

    if (producer) {
        if (w < 8) {
            // ======== layer1 recurrence, 1 gate/thread, unrolled x4 ========
            int gt = lane >> 3;
            int u  = (w << 3) + (lane & 7);
            int gidx = gt * 64 + u;
            ull wv[32];
#pragma unroll
            for (int k = 0; k < 32; k++)
                wv[k] = pack64(__ldg(Whh1 + (size_t)gidx * 64 + 2 * k),
                               __ldg(Whh1 + (size_t)gidx * 64 + 2 * k + 1));
            if (tid < 64) ring[7][tid] = 0.0f;             // h(-1) = 0
            float c = 0.0f;
            const float* xgp = g_xg1 + (size_t)b * TSTEPS * G4 + gidx;
            bar_rec256();                                  // ring init visible
            float xr[4];
#pragma unroll
            for (int p = 0; p < 4; p++) xr[p] = __ldg(xgp + (size_t)p * G4);
            for (int t0 = 0; t0 < TSTEPS; t0 += 4) {
#pragma unroll
                for (int p = 0; p < 4; p++) {
                    int t = t0 + p;
                    float xc = xr[p];
                    if (t + 4 < TSTEPS)                     // reload for t+4
                        xr[p] = __ldg(xgp + (size_t)(t + 4) * G4);
                    float pre = dot32p(ring[(t + 7) & 7], wv) + xc;
                    float A = (gt == 2) ? tanh_mufu(pre) : sig_mufu(pre);
                    float fA = __shfl_xor_sync(0xffffffffu, A, 8);
                    float gA = __shfl_xor_sync(0xffffffffu, A, 16);
                    float oA = __shfl_xor_sync(0xffffffffu, A, 24);
                    if (lane < 8) {                         // i-lanes own unit u
                        c = fA * c + A * gA;
                        float h = oA * tanh_mufu(c);
                        ring[t & 7][u] = h;
                    }
                    bar_rec256();                           // rec-only, per step
                }
                __syncthreads();                            // joint, every 4
            }
            __syncthreads();                                // final joint
        } else {
            // ======== GEMV warps: 4 xg2 rows per superstep ========
            int s = tid - 256;                              // gate 0..255
            ull wv2[32];
#pragma unroll
            for (int k = 0; k < 32; k++) {
                float m0 = __ldg(mask1 + b * 64 + 2 * k);
                float m1 = __ldg(mask1 + b * 64 + 2 * k + 1);
                wv2[k] = pack64(__ldg(Wih2 + (size_t)s * 64 + 2 * k) * m0,
                                __ldg(Wih2 + (size_t)s * 64 + 2 * k + 1) * m1);
            }
            float bias = __ldg(bih2 + s) + __ldg(bhh2 + s);
            float* dst = g_xg2 + (size_t)b * TSTEPS * G4 + s;
            for (int kk = 1; kk <= TSTEPS / 4; kk++) {
                __syncthreads();                            // joint barrier kk
                int r0 = 4 * (kk - 1);
                if (tid == 256 && r0 > 0) {
                    __threadfence();
                    st_rel(&g_flag[b], (unsigned)r0);       // rows 0..r0-1 ready
                }
#pragma unroll
                for (int j = 0; j < 4; j++)
                    dst[(size_t)(r0 + j) * G4] = dot32p(ring[(r0 + j) & 7], wv2) + bias;
            }
            __syncthreads();                                // final joint
            if (tid == 256) {
                __threadfence();
                st_rel(&g_flag[b], (unsigned)TSTEPS);
            }
        }
    } else {
        // ======== consumer: layer2 recurrence, 1 gate/thread ========
        if (w >= 8) return;                                 // warps 8-15 exit
        int gt = lane >> 3;
        int u  = (w << 3) + (lane & 7);
        int gidx = gt * 64 + u;
        ull wv[32];
#pragma unroll
        for (int k = 0; k < 32; k++)
            wv[k] = pack64(__ldg(Whh2 + (size_t)gidx * 64 + 2 * k),
                           __ldg(Whh2 + (size_t)gidx * 64 + 2 * k + 1));
        float mval = (lane < 8) ? __ldg(mask2 + b * 64 + u) : 0.0f;
        if (tid < 64) ring[7][tid] = 0.0f;
        float c = 0.0f;
        const float* xgp = g_xg2 + (size_t)b * TSTEPS * G4 + gidx;
        unsigned avail = 0;
        bar_rec256();
        while (avail < 4u) { avail = ld_acq(&g_flag[b]); if (avail < 4u) __nanosleep(64); }
        float xr[4];
#pragma unroll
        for (int p = 0; p < 4; p++) xr[p] = xgp[(size_t)p * G4];   // PLAIN
        for (int t0 = 0; t0 < TSTEPS; t0 += 4) {
            if (t0 + 4 < TSTEPS) {
                unsigned need = (unsigned)(t0 + 8 > TSTEPS ? TSTEPS : t0 + 8);
                while (avail < need) { avail = ld_acq(&g_flag[b]); if (avail < need) __nanosleep(64); }
            }
#pragma unroll
            for (int p = 0; p < 4; p++) {
                int t = t0 + p;
                float xc = xr[p];
                if (t + 4 < TSTEPS)
                    xr[p] = xgp[(size_t)(t + 4) * G4];      // PLAIN load
                float pre = dot32p(ring[(t + 7) & 7], wv) + xc;
                float A = (gt == 2) ? tanh_mufu(pre) : sig_mufu(pre);
                float fA = __shfl_xor_sync(0xffffffffu, A, 8);
                float gA = __shfl_xor_sync(0xffffffffu, A, 16);
                float oA = __shfl_xor_sync(0xffffffffu, A, 24);
                if (lane < 8) {
                    c = fA * c + A * gA;
                    float h = oA * tanh_mufu(c);
                    ring[t & 7][u] = h;
                    out[((size_t)b * TSTEPS + t) * HID + u] = fmaxf(h * mval, 0.0f);
                }
                bar_rec256();
            }
        }
    }
}

// ---------------------------------------------------------------------------
// Launch
// ---------------------------------------------------------------------------
extern "C" void kernel_launch(void* const* d_in, const int* in_sizes, int n_in,
                              void* d_out, int out_size) {
    const float* x     = (const float*)d_in[0];
    const float* W_ih1 = (const float*)d_in[1];
    const float* W_hh1 = (const float*)d_in[2];
    const float* b_ih1 = (const float*)d_in[3];
    const float* b_hh1 = (const float*)d_in[4];
    const float* W_ih2 = (const float*)d_in[5];
    const float* W_hh2 = (const float*)d_in[6];
    const float* b_ih2 = (const float*)d_in[7];
    const float* b_hh2 = (const float*)d_in[8];
    const float* mask1 = (const float*)d_in[9];
    const float* mask2 = (const float*)d_in[10];
    float* out = (float*)d_out;

    prep_x_kernel<<<(M_ROWS * 64) / 256, 256>>>(x);
    prep_w_kernel<<<(32 * 8 * 32 + 127) / 128, 128>>>(W_ih1);
    gemm_kernel<<<dim3(M_ROWS / 64, 2), 256>>>(b_ih1, b_hh1);
    fused_kernel<<<2 * BATCH, 512>>>(W_hh1, mask1, W_ih2, b_ih2, b_hh2,
                                     W_hh2, mask2, out);
}

// round 16
// speedup vs baseline: 2.1244x; 1.0157x over previous
#include <cuda_runtime.h>
#include <cuda_bf16.h>
#include <cstdint>

#define BATCH  64
#define TSTEPS 2048
#define M_ROWS (BATCH * TSTEPS)   // 131072
#define HID    64
#define G4     256
#define NGEMM  20                 // gemm CTAs (SMs 128..147)

typedef unsigned long long ull;

// ---------------------------------------------------------------------------
// Scratch
// ---------------------------------------------------------------------------
__device__ float    g_xg1[(size_t)M_ROWS * G4];   // layer1 preacts, natural layout
__device__ float    g_xg2[(size_t)M_ROWS * G4];   // layer2 preacts, natural layout
__device__ uint4    g_wf1[32 * 8 * 32];           // W_ih1 fragment-ordered (hi+lo)
__device__ unsigned g_flag[BATCH];                // xg2 rows ready per sequence
__device__ unsigned g_flag1[BATCH];               // xg1 rows ready per sequence

// ---------------------------------------------------------------------------
// Helpers
// ---------------------------------------------------------------------------
__device__ __forceinline__ uint32_t packbf(float lo, float hi) {
    uint32_t r;
    asm("cvt.rn.bf16x2.f32 %0, %1, %2;" : "=r"(r) : "f"(hi), "f"(lo));
    return r;
}
__device__ __forceinline__ ull pack64(float lo, float hi) {
    ull r; asm("mov.b64 %0, {%1, %2};" : "=l"(r) : "f"(lo), "f"(hi)); return r;
}
__device__ __forceinline__ void unpack64(ull v, float& lo, float& hi) {
    asm("mov.b64 {%0, %1}, %2;" : "=f"(lo), "=f"(hi) : "l"(v));
}
__device__ __forceinline__ void fma2(ull& acc, ull a, ull b) {
    asm("fma.rn.f32x2 %0, %1, %2, %0;" : "+l"(acc) : "l"(a), "l"(b));
}
__device__ __forceinline__ ull add2(ull a, ull b) {
    ull r; asm("add.rn.f32x2 %0, %1, %2;" : "=l"(r) : "l"(a), "l"(b)); return r;
}
__device__ __forceinline__ float bf16_round(float f) {
    return __bfloat162float(__float2bfloat16_rn(f));
}
__device__ __forceinline__ float tanh_mufu(float x) {
    float y; asm("tanh.approx.f32 %0, %1;" : "=f"(y) : "f"(x)); return y;
}
__device__ __forceinline__ float sig_mufu(float x) {
    return fmaf(tanh_mufu(x * 0.5f), 0.5f, 0.5f);
}
__device__ __forceinline__ void mma16816(float* c, const uint32_t* a,
                                         uint32_t b0, uint32_t b1) {
    asm("mma.sync.aligned.m16n8k16.row.col.f32.bf16.bf16.f32 "
        "{%0,%1,%2,%3}, {%4,%5,%6,%7}, {%8,%9}, {%0,%1,%2,%3};"
        : "+f"(c[0]), "+f"(c[1]), "+f"(c[2]), "+f"(c[3])
        : "r"(a[0]), "r"(a[1]), "r"(a[2]), "r"(a[3]), "r"(b0), "r"(b1));
}
__device__ __forceinline__ unsigned ld_acq(const unsigned* p) {
    unsigned v;
    asm volatile("ld.acquire.gpu.global.u32 %0, [%1];" : "=r"(v) : "l"(p) : "memory");
    return v;
}
__device__ __forceinline__ void st_rel(unsigned* p, unsigned v) {
    asm volatile("st.release.gpu.global.u32 [%0], %1;" :: "l"(p), "r"(v) : "memory");
}
__device__ __forceinline__ void bar_rec256() {       // rec-warps-only barrier
    asm volatile("bar.sync 1, 256;" ::: "memory");
}

// 32-FFMA2 packed dot over h[64] (float smem row), software-pipelined LDS.128.
__device__ __forceinline__ float dot32p(const float* hp_, const ull* wv) {
    const ulonglong2* hp = (const ulonglong2*)hp_;   // 16 entries
    ulonglong2 bufA[4], bufB[4];
#pragma unroll
    for (int i = 0; i < 4; i++) bufA[i] = hp[i];
    ull a0 = 0ull, a1 = 0ull, a2 = 0ull, a3 = 0ull;
#pragma unroll
    for (int c = 0; c < 4; c++) {
        ulonglong2* cur = (c & 1) ? bufB : bufA;
        ulonglong2* nxt = (c & 1) ? bufA : bufB;
        if (c < 3) {
#pragma unroll
            for (int i = 0; i < 4; i++) nxt[i] = hp[(c + 1) * 4 + i];
        }
        fma2(a0, cur[0].x, wv[c * 8 + 0]);
        fma2(a1, cur[0].y, wv[c * 8 + 1]);
        fma2(a2, cur[1].x, wv[c * 8 + 2]);
        fma2(a3, cur[1].y, wv[c * 8 + 3]);
        fma2(a0, cur[2].x, wv[c * 8 + 4]);
        fma2(a1, cur[2].y, wv[c * 8 + 5]);
        fma2(a2, cur[3].x, wv[c * 8 + 6]);
        fma2(a3, cur[3].y, wv[c * 8 + 7]);
    }
    ull s = add2(add2(a0, a1), add2(a2, a3));
    float lo, hi; unpack64(s, lo, hi);
    return lo + hi;
}

// ---------------------------------------------------------------------------
// Prep: W_ih1 fragments + flag reset (prep_x is gone; packing is in-register)
// ---------------------------------------------------------------------------
__global__ void prep_w_kernel(const float* __restrict__ W) {
    const int KI = 8, K = 128;
    int total = 32 * KI * 32;
    int i = blockIdx.x * blockDim.x + threadIdx.x;
    if (i < BATCH) { g_flag[i] = 0; g_flag1[i] = 0; }
    if (i >= total) return;
    int lane = i & 31;
    int ki   = (i >> 5) % KI;
    int nt   = i / (32 * KI);
    int tig = lane & 3, gid = lane >> 2;
    int n  = nt * 8 + gid;
    int k0 = ki * 16 + tig * 2;
    const float* Wn = W + (size_t)n * K;
    float w00 = Wn[k0],     w01 = Wn[k0 + 1];
    float w10 = Wn[k0 + 8], w11 = Wn[k0 + 9];
    uint4 v;
    v.x = packbf(w00, w01);
    v.y = packbf(w10, w11);
    v.z = packbf(w00 - bf16_round(w00), w01 - bf16_round(w01));
    v.w = packbf(w10 - bf16_round(w10), w11 - bf16_round(w11));
    g_wf1[(nt * KI + ki) * 32 + lane] = v;
}

// ---------------------------------------------------------------------------
// Mega kernel: 148 CTAs x 512 threads, single wave, three roles.
//  bid <  64 : PRODUCER  (layer1 rec + xg2 GEMV), xg1 gated on g_flag1
//  bid < 128 : CONSUMER  (layer2 rec), xg2 gated on g_flag
//  bid >=128 : GEMM      (xg1 tiles, 16 warps, in-register bf16 packing)
// ---------------------------------------------------------------------------
__global__ __launch_bounds__(512, 1) void mega_kernel(
    const float* __restrict__ x,
    const float* __restrict__ Whh1, const float* __restrict__ mask1,
    const float* __restrict__ Wih2, const float* __restrict__ bih2,
    const float* __restrict__ bhh2,
    const float* __restrict__ Whh2, const float* __restrict__ mask2,
    const float* __restrict__ bih1, const float* __restrict__ bhh1,
    float* __restrict__ out)
{
    __shared__ alignas(16) float ring[8][64];   // h history: row t at ring[t&7]

    int tid = threadIdx.x;
    int bid = blockIdx.x;
    int lane = tid & 31, w = tid >> 5;

    if (bid >= 2 * BATCH) {
        // ==================== GEMM role: xg1 tiles ====================
        int j = bid - 2 * BATCH;                            // 0..NGEMM-1
        int wm = w & 3, wn = w >> 2;                        // 4 m-slices x 4 n-quarters
        int tig = lane & 3, gid = lane >> 2;
        for (int tc = 0; tc < TSTEPS / 64; tc++) {
            for (int b = j; b < BATCH; b += NGEMM) {
                size_t rowbase = (size_t)b * TSTEPS + tc * 64 + wm * 16 + gid;
                float acc[8][4];
#pragma unroll
                for (int jl = 0; jl < 8; jl++)
#pragma unroll
                    for (int q = 0; q < 4; q++) acc[jl][q] = 0.0f;
#pragma unroll
                for (int ki = 0; ki < 8; ki++) {
                    const float* xr = x + rowbase * 128 + ki * 16 + tig * 2;
                    float2 v0 = *(const float2*)(xr);
                    float2 v1 = *(const float2*)(xr + 8 * 128);
                    float2 v2 = *(const float2*)(xr + 8);
                    float2 v3 = *(const float2*)(xr + 8 * 128 + 8);
                    uint32_t a[4], al[4];
                    a[0]  = packbf(v0.x, v0.y);
                    a[1]  = packbf(v1.x, v1.y);
                    a[2]  = packbf(v2.x, v2.y);
                    a[3]  = packbf(v3.x, v3.y);
                    al[0] = packbf(v0.x - bf16_round(v0.x), v0.y - bf16_round(v0.y));
                    al[1] = packbf(v1.x - bf16_round(v1.x), v1.y - bf16_round(v1.y));
                    al[2] = packbf(v2.x - bf16_round(v2.x), v2.y - bf16_round(v2.y));
                    al[3] = packbf(v3.x - bf16_round(v3.x), v3.y - bf16_round(v3.y));
#pragma unroll
                    for (int jl = 0; jl < 8; jl++) {
                        uint4 bf = __ldg(&g_wf1[((wn * 8 + jl) * 8 + ki) * 32 + lane]);
                        mma16816(acc[jl], a,  bf.x, bf.y);
                        mma16816(acc[jl], a,  bf.z, bf.w);
                        mma16816(acc[jl], al, bf.x, bf.y);
                    }
                }
#pragma unroll
                for (int jl = 0; jl < 8; jl++) {
                    int nc = (wn * 8 + jl) * 8 + tig * 2;
                    float bs0 = __ldg(bih1 + nc) + __ldg(bhh1 + nc);
                    float bs1 = __ldg(bih1 + nc + 1) + __ldg(bhh1 + nc + 1);
                    *(float2*)(g_xg1 + rowbase * G4 + nc) =
                        make_float2(acc[jl][0] + bs0, acc[jl][1] + bs1);
                    *(float2*)(g_xg1 + (rowbase + 8) * G4 + nc) =
                        make_float2(acc[jl][2] + bs0, acc[jl][3] + bs1);
                }
                __syncthreads();                            // tile stores done
                if (tid == 0) {
                    __threadfence();
                    st_rel(&g_flag1[b], (unsigned)((tc + 1) * 64));
                }
            }
        }
        return;
    }

    bool producer = bid < BATCH;
    int b = producer ? bid : bid - BATCH;

    if (producer) {
        if (w < 8) {
            // ======== layer1 rec, 1 gate/thread, unrolled x4, flag1-gated ====
            int gt = lane >> 3;
            int u  = (w << 3) + (lane & 7);
            int gidx = gt * 64 + u;
            ull wv[32];
#pragma unroll
            for (int k = 0; k < 32; k++)
                wv[k] = pack64(__ldg(Whh1 + (size_t)gidx * 64 + 2 * k),
                               __ldg(Whh1 + (size_t)gidx * 64 + 2 * k + 1));
            if (tid < 64) ring[7][tid] = 0.0f;             // h(-1) = 0
            float c = 0.0f;
            const float* xgp = g_xg1 + (size_t)b * TSTEPS * G4 + gidx;
            unsigned avail1 = 0;
            bar_rec256();                                  // ring init visible
            while (avail1 < 4u) { avail1 = ld_acq(&g_flag1[b]); if (avail1 < 4u) __nanosleep(64); }
            float xr[4];
#pragma unroll
            for (int p = 0; p < 4; p++) xr[p] = xgp[(size_t)p * G4];  // PLAIN
            for (int t0 = 0; t0 < TSTEPS; t0 += 4) {
                if (t0 + 4 < TSTEPS) {
                    unsigned need = (unsigned)(t0 + 8 > TSTEPS ? TSTEPS : t0 + 8);
                    while (avail1 < need) { avail1 = ld_acq(&g_flag1[b]); if (avail1 < need) __nanosleep(64); }
                }
#pragma unroll
                for (int p = 0; p < 4; p++) {
                    int t = t0 + p;
                    float xc = xr[p];
                    if (t + 4 < TSTEPS)
                        xr[p] = xgp[(size_t)(t + 4) * G4];  // PLAIN load
                    float pre = dot32p(ring[(t + 7) & 7], wv) + xc;
                    float A = (gt == 2) ? tanh_mufu(pre) : sig_mufu(pre);
                    float fA = __shfl_xor_sync(0xffffffffu, A, 8);
                    float gA = __shfl_xor_sync(0xffffffffu, A, 16);
                    float oA = __shfl_xor_sync(0xffffffffu, A, 24);
                    if (lane < 8) {                         // i-lanes own unit u
                        c = fA * c + A * gA;
                        float h = oA * tanh_mufu(c);
                        ring[t & 7][u] = h;
                    }
                    bar_rec256();                           // rec-only, per step
                }
                __syncthreads();                            // joint, every 4
            }
            __syncthreads();                                // final joint
        } else {
            // ======== GEMV warps: 4 xg2 rows per superstep ========
            int s = tid - 256;                              // gate 0..255
            ull wv2[32];
#pragma unroll
            for (int k = 0; k < 32; k++) {
                float m0 = __ldg(mask1 + b * 64 + 2 * k);
                float m1 = __ldg(mask1 + b * 64 + 2 * k + 1);
                wv2[k] = pack64(__ldg(Wih2 + (size_t)s * 64 + 2 * k) * m0,
                                __ldg(Wih2 + (size_t)s * 64 + 2 * k + 1) * m1);
            }
            float bias = __ldg(bih2 + s) + __ldg(bhh2 + s);
            float* dst = g_xg2 + (size_t)b * TSTEPS * G4 + s;
            for (int kk = 1; kk <= TSTEPS / 4; kk++) {
                __syncthreads();                            // joint barrier kk
                int r0 = 4 * (kk - 1);
                if (tid == 256 && r0 > 0) {
                    __threadfence();
                    st_rel(&g_flag[b], (unsigned)r0);       // rows 0..r0-1 ready
                }
#pragma unroll
                for (int jl = 0; jl < 4; jl++)
                    dst[(size_t)(r0 + jl) * G4] = dot32p(ring[(r0 + jl) & 7], wv2) + bias;
            }
            __syncthreads();                                // final joint
            if (tid == 256) {
                __threadfence();
                st_rel(&g_flag[b], (unsigned)TSTEPS);
            }
        }
    } else {
        // ======== consumer: layer2 recurrence, 1 gate/thread ========
        if (w >= 8) return;                                 // warps 8-15 exit
        int gt = lane >> 3;
        int u  = (w << 3) + (lane & 7);
        int gidx = gt * 64 + u;
        ull wv[32];
#pragma unroll
        for (int k = 0; k < 32; k++)
            wv[k] = pack64(__ldg(Whh2 + (size_t)gidx * 64 + 2 * k),
                           __ldg(Whh2 + (size_t)gidx * 64 + 2 * k + 1));
        float mval = (lane < 8) ? __ldg(mask2 + b * 64 + u) : 0.0f;
        if (tid < 64) ring[7][tid] = 0.0f;
        float c = 0.0f;
        const float* xgp = g_xg2 + (size_t)b * TSTEPS * G4 + gidx;
        unsigned avail = 0;
        bar_rec256();
        while (avail < 4u) { avail = ld_acq(&g_flag[b]); if (avail < 4u) __nanosleep(64); }
        float xr[4];
#pragma unroll
        for (int p = 0; p < 4; p++) xr[p] = xgp[(size_t)p * G4];   // PLAIN
        for (int t0 = 0; t0 < TSTEPS; t0 += 4) {
            if (t0 + 4 < TSTEPS) {
                unsigned need = (unsigned)(t0 + 8 > TSTEPS ? TSTEPS : t0 + 8);
                while (avail < need) { avail = ld_acq(&g_flag[b]); if (avail < need) __nanosleep(64); }
            }
#pragma unroll
            for (int p = 0; p < 4; p++) {
                int t = t0 + p;
                float xc = xr[p];
                if (t + 4 < TSTEPS)
                    xr[p] = xgp[(size_t)(t + 4) * G4];      // PLAIN load
                float pre = dot32p(ring[(t + 7) & 7], wv) + xc;
                float A = (gt == 2) ? tanh_mufu(pre) : sig_mufu(pre);
                float fA = __shfl_xor_sync(0xffffffffu, A, 8);
                float gA = __shfl_xor_sync(0xffffffffu, A, 16);
                float oA = __shfl_xor_sync(0xffffffffu, A, 24);
                if (lane < 8) {
                    c = fA * c + A * gA;
                    float h = oA * tanh_mufu(c);
                    ring[t & 7][u] = h;
                    out[((size_t)b * TSTEPS + t) * HID + u] = fmaxf(h * mval, 0.0f);
                }
                bar_rec256();
            }
        }
    }
}

// ---------------------------------------------------------------------------
// Launch
// ---------------------------------------------------------------------------
extern "C" void kernel_launch(void* const* d_in, const int* in_sizes, int n_in,
                              void* d_out, int out_size) {
    const float* x     = (const float*)d_in[0];
    const float* W_ih1 = (const float*)d_in[1];
    const float* W_hh1 = (const float*)d_in[2];
    const float* b_ih1 = (const float*)d_in[3];
    const float* b_hh1 = (const float*)d_in[4];
    const float* W_ih2 = (const float*)d_in[5];
    const float* W_hh2 = (const float*)d_in[6];
    const float* b_ih2 = (const float*)d_in[7];
    const float* b_hh2 = (const float*)d_in[8];
    const float* mask1 = (const float*)d_in[9];
    const float* mask2 = (const float*)d_in[10];
    float* out = (float*)d_out;

    prep_w_kernel<<<64, 128>>>(W_ih1);
    mega_kernel<<<2 * BATCH + NGEMM, 512>>>(x, W_hh1, mask1, W_ih2, b_ih2,
                                            b_hh2, W_hh2, mask2, b_ih1, b_hh1,
                                            out);
}